// round 14
// baseline (speedup 1.0000x reference)
#include <cuda_runtime.h>
#include <cuda_bf16.h>
#include <cuda_fp16.h>
#include <math.h>
#include <stdint.h>

#define BB   4
#define SS   512
#define HID_ 1024
#define HH   16
#define DD   64
#define NREL_ 64
#define TT   (BB*SS)      // 2048 tokens
#define BH   (BB*HH)      // 64

// ---------------- scratch (static device globals) ---------------------------
__device__ uint32_t g_Qh[BH*SS*DD/2];             // [bh][s][d] fp16
__device__ uint32_t g_Kh[BH*SS*DD/2];             // [bh][s][d] fp16
__device__ __half   g_Vh[BH*SS*DD];               // [bh][d][s] fp16 (TRANSPOSED)
__device__ float    g_prsum[BH*SS*NREL_];         // unnormalized relation bins
__device__ float    g_lsum[BH*SS];                // unnormalized row sums
__device__ uint32_t g_p16[(size_t)BH*SS*SS/2];    // unnormalized exp'd probs fp16
__device__ uint32_t g_attn16[TT*HID_/2];          // attention output fp16
// fp16 copies of GEMM inputs + rel tables
__device__ uint32_t g_rq[TT*HID_/2];
__device__ uint32_t g_rk[TT*HID_/2];
__device__ uint32_t g_rv[TT*HID_/2];
__device__ uint32_t g_wq[HID_*HID_/2];
__device__ uint32_t g_wk[HID_*HID_/2];
__device__ uint32_t g_wv[HID_*HID_/2];
__device__ uint32_t g_wo[HID_*HID_/2];
__device__ uint32_t g_relk_h[NREL_*DD/2];
__device__ __half   g_relv_h[NREL_*DD];

__device__ __forceinline__ uint32_t pack_h16(float a, float b) {
    __half2 t = __floats2half2_rn(a, b);
    return *(uint32_t*)&t;
}

// ---------------- fp32 -> fp16 conversion pass -------------------------------
struct RoundArgs {
    const float4* src[9];
    uint2*        dst[9];
    int           n4[9];
};
__global__ void round_f16_kernel(RoundArgs a)
{
    int seg = blockIdx.y;
    const float4* s = a.src[seg];
    uint2*        d = a.dst[seg];
    int n = a.n4[seg];
    for (int i = blockIdx.x * blockDim.x + threadIdx.x; i < n;
         i += gridDim.x * blockDim.x) {
        float4 v = s[i];
        uint2 o;
        o.x = pack_h16(v.x, v.y);
        o.y = pack_h16(v.z, v.w);
        d[i] = o;
    }
}

// ======================= MMA / cp.async helpers ==============================
__device__ __forceinline__ void mma_f16(float c[4], const uint32_t a[4],
                                        const uint32_t b2[2]) {
    asm volatile(
        "mma.sync.aligned.m16n8k16.row.col.f32.f16.f16.f32 "
        "{%0,%1,%2,%3}, {%4,%5,%6,%7}, {%8,%9}, {%0,%1,%2,%3};"
        : "+f"(c[0]), "+f"(c[1]), "+f"(c[2]), "+f"(c[3])
        : "r"(a[0]), "r"(a[1]), "r"(a[2]), "r"(a[3]),
          "r"(b2[0]), "r"(b2[1]));
}
__device__ __forceinline__ void cp_async16(uint32_t smem, const void* g) {
    asm volatile("cp.async.cg.shared.global [%0], [%1], 16;\n"
                 :: "r"(smem), "l"(g));
}
__device__ __forceinline__ uint32_t smem_u32(const void* p) {
    return (uint32_t)__cvta_generic_to_shared(p);
}

// ======================= fp16 tensor-core GEMM (2-stage, GBK=64, proven) =====
struct GemmArgs {
    const __half* X[3];
    const __half* W[3];
    const float*  b[3];
    void*         O[3];
    int sc[3];
};

#define GBM 128
#define GBK 64
#define GLDW 36
#define GTILE (GBM * GLDW)

__global__ void __launch_bounds__(256, 2)
h16_gemm_kernel(GemmArgs args)
{
    const int K = 1024, N = 1024;
    int mat = blockIdx.z;
    const __half* __restrict__ X    = args.X[mat];
    const __half* __restrict__ W    = args.W[mat];
    const float*  __restrict__ bias = args.b[mat];
    void*                      O    = args.O[mat];
    int sc = args.sc[mat];

    extern __shared__ uint32_t smg[];

    int tid  = threadIdx.x;
    int lane = tid & 31;
    int wid  = tid >> 5;
    int wm   = wid & 1;
    int wn   = wid >> 1;
    int gid  = lane >> 2;
    int tig  = lane & 3;

    int row0 = blockIdx.y * GBM;
    int col0 = blockIdx.x * GBM;

    uint32_t smem_base = smem_u32(smg);

    float acc[4][4][4] = {};
    const int KT = K / GBK;   // 16

    auto issue = [&](int st, int k0) {
        uint32_t xs = smem_base + (st * 2 * GTILE) * 4;
        uint32_t ws = xs + GTILE * 4;
        #pragma unroll
        for (int p = 0; p < 4; p++) {
            int ch = tid + p * 256;
            int r = ch >> 3, cq = ch & 7;
            cp_async16(xs + (r * GLDW + cq * 4) * 4,
                       X + (size_t)(row0 + r) * K + k0 + cq * 8);
            cp_async16(ws + (r * GLDW + cq * 4) * 4,
                       W + (size_t)(col0 + r) * K + k0 + cq * 8);
        }
    };

    issue(0, 0);
    asm volatile("cp.async.commit_group;\n" ::);

    for (int kt = 0; kt < KT; kt++) {
        if (kt + 1 < KT) {
            issue((kt + 1) & 1, (kt + 1) * GBK);
            asm volatile("cp.async.commit_group;\n" ::);
            asm volatile("cp.async.wait_group 1;\n" ::);
        } else {
            asm volatile("cp.async.wait_group 0;\n" ::);
        }
        __syncthreads();

        const uint32_t* Xs = smg + ((kt & 1) * 2) * GTILE;
        const uint32_t* Ws = Xs + GTILE;

        #pragma unroll
        for (int ks = 0; ks < 4; ks++) {
            int kb = ks * 8;
            uint32_t af[4][4];
            #pragma unroll
            for (int mt = 0; mt < 4; mt++) {
                int m = wm * 64 + mt * 16;
                af[mt][0] = Xs[(m + gid    ) * GLDW + kb + tig    ];
                af[mt][1] = Xs[(m + gid + 8) * GLDW + kb + tig    ];
                af[mt][2] = Xs[(m + gid    ) * GLDW + kb + tig + 4];
                af[mt][3] = Xs[(m + gid + 8) * GLDW + kb + tig + 4];
            }
            uint32_t bf[4][2];
            #pragma unroll
            for (int nt = 0; nt < 4; nt++) {
                int n = wn * 32 + nt * 8;
                bf[nt][0] = Ws[(n + gid) * GLDW + kb + tig    ];
                bf[nt][1] = Ws[(n + gid) * GLDW + kb + tig + 4];
            }
            #pragma unroll
            for (int mt = 0; mt < 4; mt++)
                #pragma unroll
                for (int nt = 0; nt < 4; nt++)
                    mma_f16(acc[mt][nt], af[mt], bf[nt]);
        }
        __syncthreads();
    }

    #pragma unroll
    for (int mt = 0; mt < 4; mt++) {
        #pragma unroll
        for (int nt = 0; nt < 4; nt++) {
            int m = row0 + wm * 64 + mt * 16 + gid;
            int n = col0 + wn * 32 + nt * 8 + tig * 2;
            float y00 = acc[mt][nt][0] + bias[n];
            float y01 = acc[mt][nt][1] + bias[n + 1];
            float y10 = acc[mt][nt][2] + bias[n];
            float y11 = acc[mt][nt][3] + bias[n + 1];
            if (sc == 1) {
                uint32_t* Oh = (uint32_t*)O;
                int b = m >> 9, s = m & 511, h = n >> 6, d = n & 63;
                Oh[((((size_t)b * HH + h) * SS + s) * DD + d) >> 1] =
                    pack_h16(y00, y01);
                int s2 = (m + 8) & 511;
                Oh[((((size_t)b * HH + h) * SS + s2) * DD + d) >> 1] =
                    pack_h16(y10, y11);
            } else if (sc == 2) {
                __half* Oh = (__half*)O;
                int b = m >> 9, s = m & 511, h = n >> 6, d = n & 63;
                size_t base = (((size_t)b * HH + h) * DD + d) * SS;
                Oh[base + s]           = __float2half(y00);
                Oh[base + SS + s]      = __float2half(y01);
                Oh[base + s + 8]       = __float2half(y10);
                Oh[base + SS + s + 8]  = __float2half(y11);
            } else {
                float* Of = (float*)O;
                *(float2*)&Of[(size_t)m * N + n]       = make_float2(y00, y01);
                *(float2*)&Of[(size_t)(m + 8) * N + n] = make_float2(y10, y11);
            }
        }
    }
}

// ====== qk_soft: CTA owns 64 rows x 512 cols; qrel + scores + exp + bins =====
// smem: Qs[64][36] | Kb[2][128][36] | qtab f32[64][68] | bins f32[64][68] | lsum[64]
#define QKW 36
#define QS_W   (64 * QKW)        // 2304
#define KB_W   (128 * QKW)       // 4608 per stage
#define QT_OFF (QS_W + 2 * KB_W)             // 11520
#define BN_OFF (QT_OFF + 64 * 68)            // 15872
#define LS_OFF (BN_OFF + 64 * 68)            // 20224
#define QKSOFT_W (LS_OFF + 64)               // 20288 words = 81152 B

__global__ void __launch_bounds__(256, 2)
qk_soft_kernel(const int* __restrict__ mask)
{
    extern __shared__ uint32_t sm2[];
    uint32_t* Qs   = sm2;
    uint32_t* Kb   = sm2 + QS_W;
    float*    qtab = (float*)(sm2 + QT_OFF);
    float*    bins = (float*)(sm2 + BN_OFF);
    float*    lsum = (float*)(sm2 + LS_OFF);

    int tid  = threadIdx.x;
    int lane = tid & 31;
    int wid  = tid >> 5;
    int wm   = wid & 1;        // 2 warps over 64 rows (32 each)
    int wn   = wid >> 1;       // 4 warps over 128 cols (32 each)
    int gid  = lane >> 2;
    int tig  = lane & 3;

    int bh   = blockIdx.y;
    int b    = bh >> 4;
    int row0 = blockIdx.x * 64;
    size_t rowg = (size_t)bh * SS + row0;

    const __half* Qg = (const __half*)g_Qh + (size_t)bh * SS * DD;
    const __half* Kg = (const __half*)g_Kh + (size_t)bh * SS * DD;

    uint32_t qs0 = smem_u32(Qs);
    uint32_t kb0 = smem_u32(Kb);

    // load Q (64 rows) + relk (64 rows) into Kb stage 0
    #pragma unroll
    for (int p = 0; p < 2; p++) {
        int ch = tid + p * 256;           // 0..511
        int r = ch >> 3, cq = ch & 7;
        cp_async16(qs0 + (r * QKW + cq * 4) * 4,
                   Qg + (size_t)(row0 + r) * DD + cq * 8);
        cp_async16(kb0 + (r * QKW + cq * 4) * 4,
                   (const __half*)g_relk_h + (size_t)r * DD + cq * 8);
    }
    asm volatile("cp.async.commit_group;\n" ::);

    // zero bins + lsum while loads fly
    for (int i = tid; i < 64 * 68; i += 256) bins[i] = 0.f;
    if (tid < 64) lsum[tid] = 0.f;

    asm volatile("cp.async.wait_group 0;\n" ::);
    __syncthreads();

    // qtab = (Q @ relk^T) / 32  (warps wn<2 cover 64 rel columns)
    if (wn < 2) {
        float acc2[2][4][4] = {};
        #pragma unroll
        for (int ks = 0; ks < 4; ks++) {
            int kb = ks * 8;
            uint32_t af[2][4];
            #pragma unroll
            for (int mt = 0; mt < 2; mt++) {
                int m = wm * 32 + mt * 16;
                af[mt][0] = Qs[(m + gid    ) * QKW + kb + tig    ];
                af[mt][1] = Qs[(m + gid + 8) * QKW + kb + tig    ];
                af[mt][2] = Qs[(m + gid    ) * QKW + kb + tig + 4];
                af[mt][3] = Qs[(m + gid + 8) * QKW + kb + tig + 4];
            }
            uint32_t bf[4][2];
            #pragma unroll
            for (int nt = 0; nt < 4; nt++) {
                int n = wn * 32 + nt * 8;
                bf[nt][0] = Kb[(n + gid) * QKW + kb + tig    ];
                bf[nt][1] = Kb[(n + gid) * QKW + kb + tig + 4];
            }
            #pragma unroll
            for (int mt = 0; mt < 2; mt++)
                #pragma unroll
                for (int nt = 0; nt < 4; nt++)
                    mma_f16(acc2[mt][nt], af[mt], bf[nt]);
        }
        const float s = 0.03125f;
        #pragma unroll
        for (int mt = 0; mt < 2; mt++) {
            #pragma unroll
            for (int nt = 0; nt < 4; nt++) {
                int m0 = wm * 32 + mt * 16 + gid;
                int n  = wn * 32 + nt * 8 + tig * 2;
                qtab[m0 * 68 + n]           = acc2[mt][nt][0] * s;
                qtab[m0 * 68 + n + 1]       = acc2[mt][nt][1] * s;
                qtab[(m0 + 8) * 68 + n]     = acc2[mt][nt][2] * s;
                qtab[(m0 + 8) * 68 + n + 1] = acc2[mt][nt][3] * s;
            }
        }
    }
    __syncthreads();

    // K pipeline over 4 col tiles of 128
    auto issueK = [&](int st, int ct) {
        uint32_t ks = kb0 + (st * KB_W) * 4;
        #pragma unroll
        for (int p = 0; p < 4; p++) {
            int ch = tid + p * 256;       // 0..1023
            int r = ch >> 3, cq = ch & 7;
            cp_async16(ks + (r * QKW + cq * 4) * 4,
                       Kg + (size_t)(ct * 128 + r) * DD + cq * 8);
        }
    };

    issueK(0, 0);
    asm volatile("cp.async.commit_group;\n" ::);

    float rs[2][2] = {};   // row-sum partials [mt][half]
    uint32_t* Og = g_p16 + (size_t)bh * SS * (SS / 2);
    const int* mbase = mask + ((size_t)b * SS + row0) * SS;

    for (int ct = 0; ct < 4; ct++) {
        if (ct + 1 < 4) {
            issueK((ct + 1) & 1, ct + 1);
            asm volatile("cp.async.commit_group;\n" ::);
            asm volatile("cp.async.wait_group 1;\n" ::);
        } else {
            asm volatile("cp.async.wait_group 0;\n" ::);
        }
        __syncthreads();

        const uint32_t* Ks = Kb + (ct & 1) * KB_W;

        float acc[2][4][4] = {};
        #pragma unroll
        for (int ks = 0; ks < 4; ks++) {
            int kb = ks * 8;
            uint32_t af[2][4];
            #pragma unroll
            for (int mt = 0; mt < 2; mt++) {
                int m = wm * 32 + mt * 16;
                af[mt][0] = Qs[(m + gid    ) * QKW + kb + tig    ];
                af[mt][1] = Qs[(m + gid + 8) * QKW + kb + tig    ];
                af[mt][2] = Qs[(m + gid    ) * QKW + kb + tig + 4];
                af[mt][3] = Qs[(m + gid + 8) * QKW + kb + tig + 4];
            }
            uint32_t bf[4][2];
            #pragma unroll
            for (int nt = 0; nt < 4; nt++) {
                int n = wn * 32 + nt * 8;
                bf[nt][0] = Ks[(n + gid) * QKW + kb + tig    ];
                bf[nt][1] = Ks[(n + gid) * QKW + kb + tig + 4];
            }
            #pragma unroll
            for (int mt = 0; mt < 2; mt++)
                #pragma unroll
                for (int nt = 0; nt < 4; nt++)
                    mma_f16(acc[mt][nt], af[mt], bf[nt]);
        }

        // transform: exp + mask + bins + row sums; write unnormalized probs
        #pragma unroll
        for (int mt = 0; mt < 2; mt++) {
            int m0 = wm * 32 + mt * 16 + gid;
            int m1 = m0 + 8;
            #pragma unroll
            for (int nt = 0; nt < 4; nt++) {
                int n  = wn * 32 + nt * 8 + tig * 2;
                int nc = ct * 128 + n;
                int2 ia = *(const int2*)&mbase[(size_t)m0 * SS + nc];
                int2 ib = *(const int2*)&mbase[(size_t)m1 * SS + nc];
                float p0 = 0.f, p1 = 0.f, p2 = 0.f, p3 = 0.f;
                if (ia.x > 0) {
                    p0 = __expf(fmaf(acc[mt][nt][0], 0.125f, qtab[m0 * 68 + ia.x]));
                    atomicAdd(&bins[m0 * 68 + ia.x], p0);
                }
                if (ia.y > 0) {
                    p1 = __expf(fmaf(acc[mt][nt][1], 0.125f, qtab[m0 * 68 + ia.y]));
                    atomicAdd(&bins[m0 * 68 + ia.y], p1);
                }
                if (ib.x > 0) {
                    p2 = __expf(fmaf(acc[mt][nt][2], 0.125f, qtab[m1 * 68 + ib.x]));
                    atomicAdd(&bins[m1 * 68 + ib.x], p2);
                }
                if (ib.y > 0) {
                    p3 = __expf(fmaf(acc[mt][nt][3], 0.125f, qtab[m1 * 68 + ib.y]));
                    atomicAdd(&bins[m1 * 68 + ib.y], p3);
                }
                rs[mt][0] += p0 + p1;
                rs[mt][1] += p2 + p3;
                Og[((size_t)(row0 + m0) * SS + nc) >> 1] = pack_h16(p0, p1);
                Og[((size_t)(row0 + m1) * SS + nc) >> 1] = pack_h16(p2, p3);
            }
        }
        __syncthreads();
    }

    // row sums: reduce over tig quad, smem-accumulate over wn warps
    #pragma unroll
    for (int mt = 0; mt < 2; mt++) {
        #pragma unroll
        for (int h = 0; h < 2; h++) {
            float v = rs[mt][h];
            v += __shfl_xor_sync(0xffffffffu, v, 1);
            v += __shfl_xor_sync(0xffffffffu, v, 2);
            if (tig == 0)
                atomicAdd(&lsum[wm * 32 + mt * 16 + gid + h * 8], v);
        }
    }
    __syncthreads();

    // export lsum + bins (exclusive rows -> plain stores)
    if (tid < 64) g_lsum[rowg + tid] = lsum[tid];
    for (int i = tid; i < 64 * 64; i += 256) {
        int r = i >> 6, c = i & 63;
        g_prsum[(rowg + r) * NREL_ + c] = bins[r * 68 + c];
    }
}

// == av: O = (P @ V + 0.25 * prsum @ rel_v) / l   (fp16 MMA, deferred norm) ==
#define AVW 36
#define AVPT (128 * AVW)
#define AVVT (64 * AVW)
#define AVST (AVPT + AVVT)

__global__ void __launch_bounds__(256)
av_kernel()
{
    extern __shared__ uint32_t sm3[];

    int tid  = threadIdx.x;
    int lane = tid & 31;
    int wid  = tid >> 5;
    int wm   = wid & 1;
    int wn   = wid >> 1;
    int gid  = lane >> 2;
    int tig  = lane & 3;

    int bh = blockIdx.y;
    int q0 = blockIdx.x * 128;
    int b  = bh >> 4, h = bh & 15;
    size_t rowg = (size_t)bh * SS + q0;

    uint32_t smem_base = smem_u32(sm3);

    const __half* Pg = (const __half*)g_p16 + (size_t)bh * SS * SS;
    const __half* Vg = g_Vh + (size_t)bh * SS * DD;   // [d][s]

    auto issue = [&](int st, int kt) {
        uint32_t ps = smem_base + (st * AVST) * 4;
        uint32_t vs = ps + AVPT * 4;
        if (kt < 8) {
            #pragma unroll
            for (int p = 0; p < 4; p++) {
                int ch = tid + p * 256;
                int r = ch >> 3, cq = ch & 7;
                cp_async16(ps + (r * AVW + cq * 4) * 4,
                           Pg + (size_t)(q0 + r) * SS + kt * 64 + cq * 8);
            }
            #pragma unroll
            for (int p = 0; p < 2; p++) {
                int ch = tid + p * 256;
                int r = ch >> 3, cq = ch & 7;
                cp_async16(vs + (r * AVW + cq * 4) * 4,
                           Vg + (size_t)r * SS + kt * 64 + cq * 8);
            }
        } else {
            // P tile <- 0.25 * prsum (fp32 -> fp16)
            uint32_t* psw = sm3 + st * AVST;
            const float2* PR2 = (const float2*)(g_prsum + rowg * NREL_);
            #pragma unroll
            for (int p = 0; p < 16; p++) {
                int idx = tid + p * 256;       // 0..4095
                int r = idx >> 5, w = idx & 31;
                float2 v = PR2[r * 32 + w];
                psw[r * AVW + w] = pack_h16(0.25f * v.x, 0.25f * v.y);
            }
            // V tile <- rel_v transposed
            uint32_t* vsp = sm3 + st * AVST + AVPT;
            #pragma unroll
            for (int p = 0; p < 8; p++) {
                int idx = tid + p * 256;       // 0..2047
                int d = idx >> 5, w = idx & 31;
                float v0 = __half2float(g_relv_h[(size_t)(2 * w) * DD + d]);
                float v1 = __half2float(g_relv_h[(size_t)(2 * w + 1) * DD + d]);
                vsp[d * AVW + w] = pack_h16(v0, v1);
            }
        }
    };

    float acc[4][4] = {};
    float acc2[4][4] = {};

    issue(0, 0);
    asm volatile("cp.async.commit_group;\n" ::);

    for (int kt = 0; kt < 9; kt++) {
        if (kt + 1 < 9) {
            issue((kt + 1) & 1, kt + 1);
            asm volatile("cp.async.commit_group;\n" ::);
            asm volatile("cp.async.wait_group 1;\n" ::);
        } else {
            asm volatile("cp.async.wait_group 0;\n" ::);
        }
        __syncthreads();

        const uint32_t* Ps = sm3 + (kt & 1) * AVST;
        const uint32_t* Vs = Ps + AVPT;

        #pragma unroll
        for (int ks = 0; ks < 4; ks++) {
            int kb = ks * 8;
            uint32_t af[4][4];
            #pragma unroll
            for (int mt = 0; mt < 4; mt++) {
                int m = wm * 64 + mt * 16;
                af[mt][0] = Ps[(m + gid    ) * AVW + kb + tig    ];
                af[mt][1] = Ps[(m + gid + 8) * AVW + kb + tig    ];
                af[mt][2] = Ps[(m + gid    ) * AVW + kb + tig + 4];
                af[mt][3] = Ps[(m + gid + 8) * AVW + kb + tig + 4];
            }
            uint32_t bf0[2], bf1[2];
            int n0 = wn * 16;
            bf0[0] = Vs[(n0 + gid    ) * AVW + kb + tig    ];
            bf0[1] = Vs[(n0 + gid    ) * AVW + kb + tig + 4];
            bf1[0] = Vs[(n0 + 8 + gid) * AVW + kb + tig    ];
            bf1[1] = Vs[(n0 + 8 + gid) * AVW + kb + tig + 4];
            #pragma unroll
            for (int mt = 0; mt < 4; mt++) {
                mma_f16(acc[mt],  af[mt], bf0);
                mma_f16(acc2[mt], af[mt], bf1);
            }
        }
        __syncthreads();
    }

    #pragma unroll
    for (int mt = 0; mt < 4; mt++) {
        int ml = wm * 64 + mt * 16 + gid;
        int qa = q0 + ml;
        float inv0 = 1.f / g_lsum[rowg + ml];
        float inv1 = 1.f / g_lsum[rowg + ml + 8];
        int n0 = wn * 16 + tig * 2;
        size_t w0 = (((size_t)b * SS + qa    ) * HID_ + h * DD + n0) >> 1;
        size_t w1 = (((size_t)b * SS + qa + 8) * HID_ + h * DD + n0) >> 1;
        g_attn16[w0]     = pack_h16(acc[mt][0] * inv0,  acc[mt][1] * inv0);
        g_attn16[w0 + 4] = pack_h16(acc2[mt][0] * inv0, acc2[mt][1] * inv0);
        g_attn16[w1]     = pack_h16(acc[mt][2] * inv1,  acc[mt][3] * inv1);
        g_attn16[w1 + 4] = pack_h16(acc2[mt][2] * inv1, acc2[mt][3] * inv1);
    }
}

// ---------------- launch -----------------------------------------------------
extern "C" void kernel_launch(void* const* d_in, const int* in_sizes, int n_in,
                              void* d_out, int out_size)
{
    const float* q_in = (const float*)d_in[0];
    const float* k_in = (const float*)d_in[1];
    const float* v_in = (const float*)d_in[2];
    const int*   mask = (const int*)  d_in[3];
    const float* Wq   = (const float*)d_in[4];
    const float* bq   = (const float*)d_in[5];
    const float* Wk   = (const float*)d_in[6];
    const float* bk   = (const float*)d_in[7];
    const float* Wv   = (const float*)d_in[8];
    const float* bv   = (const float*)d_in[9];
    const float* Wo   = (const float*)d_in[10];
    const float* bo   = (const float*)d_in[11];
    const float* relk = (const float*)d_in[12];
    const float* relv = (const float*)d_in[13];
    float* out = (float*)d_out;

    void *pQ, *pK, *pV, *pAttn;
    void *pRq, *pRk, *pRv, *pWq, *pWk, *pWv, *pWo, *pRelk, *pRelv;
    cudaGetSymbolAddress(&pQ,    g_Qh);
    cudaGetSymbolAddress(&pK,    g_Kh);
    cudaGetSymbolAddress(&pV,    g_Vh);
    cudaGetSymbolAddress(&pAttn, g_attn16);
    cudaGetSymbolAddress(&pRq,   g_rq);
    cudaGetSymbolAddress(&pRk,   g_rk);
    cudaGetSymbolAddress(&pRv,   g_rv);
    cudaGetSymbolAddress(&pWq,   g_wq);
    cudaGetSymbolAddress(&pWk,   g_wk);
    cudaGetSymbolAddress(&pWv,   g_wv);
    cudaGetSymbolAddress(&pWo,   g_wo);
    cudaGetSymbolAddress(&pRelk, g_relk_h);
    cudaGetSymbolAddress(&pRelv, g_relv_h);

    // 1) fp32 -> fp16 conversion
    RoundArgs ra;
    ra.src[0] = (const float4*)q_in; ra.dst[0] = (uint2*)pRq; ra.n4[0] = TT*HID_/4;
    ra.src[1] = (const float4*)k_in; ra.dst[1] = (uint2*)pRk; ra.n4[1] = TT*HID_/4;
    ra.src[2] = (const float4*)v_in; ra.dst[2] = (uint2*)pRv; ra.n4[2] = TT*HID_/4;
    ra.src[3] = (const float4*)Wq;   ra.dst[3] = (uint2*)pWq; ra.n4[3] = HID_*HID_/4;
    ra.src[4] = (const float4*)Wk;   ra.dst[4] = (uint2*)pWk; ra.n4[4] = HID_*HID_/4;
    ra.src[5] = (const float4*)Wv;   ra.dst[5] = (uint2*)pWv; ra.n4[5] = HID_*HID_/4;
    ra.src[6] = (const float4*)Wo;   ra.dst[6] = (uint2*)pWo; ra.n4[6] = HID_*HID_/4;
    ra.src[7] = (const float4*)relk; ra.dst[7] = (uint2*)pRelk; ra.n4[7] = NREL_*DD/4;
    ra.src[8] = (const float4*)relv; ra.dst[8] = (uint2*)pRelv; ra.n4[8] = NREL_*DD/4;
    round_f16_kernel<<<dim3(512, 9), 256>>>(ra);

    const int gemmSmem = 2 * 2 * GTILE * 4;   // 73728 B
    cudaFuncSetAttribute(h16_gemm_kernel,
                         cudaFuncAttributeMaxDynamicSharedMemorySize, gemmSmem);

    // 2) fused QKV projection (V stored transposed per head)
    GemmArgs qkv;
    qkv.X[0] = (const __half*)pRq; qkv.X[1] = (const __half*)pRk; qkv.X[2] = (const __half*)pRv;
    qkv.W[0] = (const __half*)pWq; qkv.W[1] = (const __half*)pWk; qkv.W[2] = (const __half*)pWv;
    qkv.b[0] = bq;  qkv.b[1] = bk;  qkv.b[2] = bv;
    qkv.O[0] = pQ;  qkv.O[1] = pK;  qkv.O[2] = pV;
    qkv.sc[0] = 1;  qkv.sc[1] = 1;  qkv.sc[2] = 2;
    h16_gemm_kernel<<<dim3(HID_ / GBM, TT / GBM, 3), 256, gemmSmem>>>(qkv);

    // 3) fused qrel + scores + softmax-exp + bins (CTA-exclusive row stripes)
    const int qkSmem = QKSOFT_W * 4;   // 81152 B -> 2 CTA/SM
    cudaFuncSetAttribute(qk_soft_kernel,
                         cudaFuncAttributeMaxDynamicSharedMemorySize, qkSmem);
    qk_soft_kernel<<<dim3(8, BH), 256, qkSmem>>>(mask);

    // 4) AV + relation-V + deferred normalization
    const int avSmem = 2 * AVST * 4;   // 55296 B
    cudaFuncSetAttribute(av_kernel,
                         cudaFuncAttributeMaxDynamicSharedMemorySize, avSmem);
    av_kernel<<<dim3(4, BH), 256, avSmem>>>();

    // 5) output projection (fp32 out)
    GemmArgs og;
    og.X[0] = (const __half*)pAttn; og.W[0] = (const __half*)pWo;
    og.b[0] = bo; og.O[0] = out;
    og.X[1] = og.X[2] = nullptr; og.W[1] = og.W[2] = nullptr;
    og.b[1] = og.b[2] = nullptr; og.O[1] = og.O[2] = nullptr;
    og.sc[0] = 0; og.sc[1] = 0; og.sc[2] = 0;
    h16_gemm_kernel<<<dim3(HID_ / GBM, TT / GBM, 1), 256, gemmSmem>>>(og);
}

// round 15
// speedup vs baseline: 1.0817x; 1.0817x over previous
#include <cuda_runtime.h>
#include <cuda_bf16.h>
#include <cuda_fp16.h>
#include <math.h>
#include <stdint.h>

#define BB   4
#define SS   512
#define HID_ 1024
#define HH   16
#define DD   64
#define NREL_ 64
#define TT   (BB*SS)      // 2048 tokens
#define BH   (BB*HH)      // 64

// ---------------- scratch (static device globals; fp16 packed in uint32) ----
__device__ uint32_t g_Qh[BH*SS*DD/2];             // [bh][s][d] fp16
__device__ uint32_t g_Kh[BH*SS*DD/2];             // [bh][s][d] fp16
__device__ __half   g_Vh[BH*SS*DD];               // [bh][d][s] fp16 (TRANSPOSED)
__device__ float    g_qrel[BH*SS*NREL_];          // fp32
__device__ uint32_t g_pr16[BH*SS*NREL_/2];        // 0.25-scaled, fp16
__device__ uint32_t g_s16[(size_t)BH*SS*SS/2];    // raw scores fp16 (32 MB)
__device__ uint32_t g_p16[(size_t)BH*SS*SS/2];    // probs fp16 (32 MB)
__device__ uint32_t g_attn16[TT*HID_/2];          // attention output fp16
// fp16 copies of GEMM inputs + rel tables
__device__ uint32_t g_rq[TT*HID_/2];
__device__ uint32_t g_rk[TT*HID_/2];
__device__ uint32_t g_rv[TT*HID_/2];
__device__ uint32_t g_wq[HID_*HID_/2];
__device__ uint32_t g_wk[HID_*HID_/2];
__device__ uint32_t g_wv[HID_*HID_/2];
__device__ uint32_t g_wo[HID_*HID_/2];
__device__ uint32_t g_relk_h[NREL_*DD/2];
__device__ __half   g_relv_h[NREL_*DD];

__device__ __forceinline__ uint32_t pack_h16(float a, float b) {
    __half2 t = __floats2half2_rn(a, b);
    return *(uint32_t*)&t;
}

// ---------------- fp32 -> fp16 conversion pass -------------------------------
struct RoundArgs {
    const float4* src[9];
    uint2*        dst[9];
    int           n4[9];
};
__global__ void round_f16_kernel(RoundArgs a)
{
    int seg = blockIdx.y;
    const float4* s = a.src[seg];
    uint2*        d = a.dst[seg];
    int n = a.n4[seg];
    for (int i = blockIdx.x * blockDim.x + threadIdx.x; i < n;
         i += gridDim.x * blockDim.x) {
        float4 v = s[i];
        uint2 o;
        o.x = pack_h16(v.x, v.y);
        o.y = pack_h16(v.z, v.w);
        d[i] = o;
    }
}

// ======================= MMA / cp.async helpers ==============================
__device__ __forceinline__ void mma_f16(float c[4], const uint32_t a[4],
                                        const uint32_t b2[2]) {
    asm volatile(
        "mma.sync.aligned.m16n8k16.row.col.f32.f16.f16.f32 "
        "{%0,%1,%2,%3}, {%4,%5,%6,%7}, {%8,%9}, {%0,%1,%2,%3};"
        : "+f"(c[0]), "+f"(c[1]), "+f"(c[2]), "+f"(c[3])
        : "r"(a[0]), "r"(a[1]), "r"(a[2]), "r"(a[3]),
          "r"(b2[0]), "r"(b2[1]));
}
__device__ __forceinline__ void cp_async16(uint32_t smem, const void* g) {
    asm volatile("cp.async.cg.shared.global [%0], [%1], 16;\n"
                 :: "r"(smem), "l"(g));
}
__device__ __forceinline__ uint32_t smem_u32(const void* p) {
    return (uint32_t)__cvta_generic_to_shared(p);
}

// ======================= fp16 tensor-core GEMM (2-stage, GBK=64) =============
struct GemmArgs {
    const __half* X[3];
    const __half* W[3];
    const float*  b[3];
    void*         O[3];
    int sc[3];
};

#define GBM 128
#define GBK 64                 // halfs per k-tile
#define GLDW 36                // uint32 per smem row (32 data + 4 pad)
#define GTILE (GBM * GLDW)     // words per matrix per stage

__global__ void __launch_bounds__(256, 2)
h16_gemm_kernel(GemmArgs args)
{
    const int K = 1024, N = 1024;
    int mat = blockIdx.z;
    const __half* __restrict__ X    = args.X[mat];
    const __half* __restrict__ W    = args.W[mat];
    const float*  __restrict__ bias = args.b[mat];
    void*                      O    = args.O[mat];
    int sc = args.sc[mat];

    extern __shared__ uint32_t smg[];   // [2 stages][2 mats][128][36]

    int tid  = threadIdx.x;
    int lane = tid & 31;
    int wid  = tid >> 5;
    int wm   = wid & 1;
    int wn   = wid >> 1;
    int gid  = lane >> 2;
    int tig  = lane & 3;

    int row0 = blockIdx.y * GBM;
    int col0 = blockIdx.x * GBM;

    uint32_t smem_base = smem_u32(smg);

    float acc[4][4][4] = {};
    const int KT = K / GBK;   // 16

    auto issue = [&](int st, int k0) {
        uint32_t xs = smem_base + (st * 2 * GTILE) * 4;
        uint32_t ws = xs + GTILE * 4;
        #pragma unroll
        for (int p = 0; p < 4; p++) {
            int ch = tid + p * 256;        // 0..1023
            int r = ch >> 3, cq = ch & 7;  // 8 chunks of 8 halfs per row
            cp_async16(xs + (r * GLDW + cq * 4) * 4,
                       X + (size_t)(row0 + r) * K + k0 + cq * 8);
            cp_async16(ws + (r * GLDW + cq * 4) * 4,
                       W + (size_t)(col0 + r) * K + k0 + cq * 8);
        }
    };

    issue(0, 0);
    asm volatile("cp.async.commit_group;\n" ::);

    for (int kt = 0; kt < KT; kt++) {
        if (kt + 1 < KT) {
            issue((kt + 1) & 1, (kt + 1) * GBK);
            asm volatile("cp.async.commit_group;\n" ::);
            asm volatile("cp.async.wait_group 1;\n" ::);
        } else {
            asm volatile("cp.async.wait_group 0;\n" ::);
        }
        __syncthreads();

        const uint32_t* Xs = smg + ((kt & 1) * 2) * GTILE;
        const uint32_t* Ws = Xs + GTILE;

        #pragma unroll
        for (int ks = 0; ks < 4; ks++) {
            int kb = ks * 8;
            uint32_t af[4][4];
            #pragma unroll
            for (int mt = 0; mt < 4; mt++) {
                int m = wm * 64 + mt * 16;
                af[mt][0] = Xs[(m + gid    ) * GLDW + kb + tig    ];
                af[mt][1] = Xs[(m + gid + 8) * GLDW + kb + tig    ];
                af[mt][2] = Xs[(m + gid    ) * GLDW + kb + tig + 4];
                af[mt][3] = Xs[(m + gid + 8) * GLDW + kb + tig + 4];
            }
            uint32_t bf[4][2];
            #pragma unroll
            for (int nt = 0; nt < 4; nt++) {
                int n = wn * 32 + nt * 8;
                bf[nt][0] = Ws[(n + gid) * GLDW + kb + tig    ];
                bf[nt][1] = Ws[(n + gid) * GLDW + kb + tig + 4];
            }
            #pragma unroll
            for (int mt = 0; mt < 4; mt++)
                #pragma unroll
                for (int nt = 0; nt < 4; nt++)
                    mma_f16(acc[mt][nt], af[mt], bf[nt]);
        }
        __syncthreads();
    }

    #pragma unroll
    for (int mt = 0; mt < 4; mt++) {
        #pragma unroll
        for (int nt = 0; nt < 4; nt++) {
            int m = row0 + wm * 64 + mt * 16 + gid;
            int n = col0 + wn * 32 + nt * 8 + tig * 2;
            float y00 = acc[mt][nt][0] + bias[n];
            float y01 = acc[mt][nt][1] + bias[n + 1];
            float y10 = acc[mt][nt][2] + bias[n];
            float y11 = acc[mt][nt][3] + bias[n + 1];
            if (sc == 1) {
                uint32_t* Oh = (uint32_t*)O;
                int b = m >> 9, s = m & 511, h = n >> 6, d = n & 63;
                Oh[((((size_t)b * HH + h) * SS + s) * DD + d) >> 1] =
                    pack_h16(y00, y01);
                int s2 = (m + 8) & 511;
                Oh[((((size_t)b * HH + h) * SS + s2) * DD + d) >> 1] =
                    pack_h16(y10, y11);
            } else if (sc == 2) {
                __half* Oh = (__half*)O;
                int b = m >> 9, s = m & 511, h = n >> 6, d = n & 63;
                size_t base = (((size_t)b * HH + h) * DD + d) * SS;
                Oh[base + s]           = __float2half(y00);
                Oh[base + SS + s]      = __float2half(y01);
                Oh[base + s + 8]       = __float2half(y10);
                Oh[base + SS + s + 8]  = __float2half(y11);
            } else {
                float* Of = (float*)O;
                *(float2*)&Of[(size_t)m * N + n]       = make_float2(y00, y01);
                *(float2*)&Of[(size_t)(m + 8) * N + n] = make_float2(y10, y11);
            }
        }
    }
}

// ================= qk_scores (+fused qrel): fp16 MMA =========================
#define QKW 36    // uint32 per smem row (32 data + 4 pad)

__global__ void __launch_bounds__(256, 2)
qk_scores_kernel()
{
    extern __shared__ uint32_t sm2[];   // Qs[128][36] Ks[128][36] Rs[64][36]
    uint32_t* Qs = sm2;
    uint32_t* Ks = sm2 + 128 * QKW;
    uint32_t* Rs = sm2 + 256 * QKW;

    int tid  = threadIdx.x;
    int lane = tid & 31;
    int wid  = tid >> 5;
    int wm   = wid & 1;
    int wn   = wid >> 1;
    int gid  = lane >> 2;
    int tig  = lane & 3;

    int bh   = blockIdx.z;
    int row0 = blockIdx.y * 128;
    int col0 = blockIdx.x * 128;

    const __half* Qg = (const __half*)g_Qh + (size_t)bh * SS * DD;
    const __half* Kg = (const __half*)g_Kh + (size_t)bh * SS * DD;

    uint32_t qs0 = smem_u32(Qs);
    uint32_t ks0 = smem_u32(Ks);
    uint32_t rs0 = smem_u32(Rs);

    #pragma unroll
    for (int p = 0; p < 4; p++) {
        int ch = tid + p * 256;
        int r = ch >> 3, cq = ch & 7;
        cp_async16(qs0 + (r * QKW + cq * 4) * 4,
                   Qg + (size_t)(row0 + r) * DD + cq * 8);
        cp_async16(ks0 + (r * QKW + cq * 4) * 4,
                   Kg + (size_t)(col0 + r) * DD + cq * 8);
    }
    if (col0 == 0) {
        #pragma unroll
        for (int p = 0; p < 2; p++) {
            int ch = tid + p * 256;
            int r = ch >> 3, cq = ch & 7;
            cp_async16(rs0 + (r * QKW + cq * 4) * 4,
                       (const __half*)g_relk_h + (size_t)r * DD + cq * 8);
        }
    }
    asm volatile("cp.async.commit_group;\n" ::);
    asm volatile("cp.async.wait_group 0;\n" ::);
    __syncthreads();

    // fused qrel (only first n-tile; warps wn<2 cover the 64 rel columns)
    if (col0 == 0 && wn < 2) {
        float acc2[4][4][4] = {};
        #pragma unroll
        for (int ks = 0; ks < 4; ks++) {
            int kb = ks * 8;
            uint32_t af[4][4];
            #pragma unroll
            for (int mt = 0; mt < 4; mt++) {
                int m = wm * 64 + mt * 16;
                af[mt][0] = Qs[(m + gid    ) * QKW + kb + tig    ];
                af[mt][1] = Qs[(m + gid + 8) * QKW + kb + tig    ];
                af[mt][2] = Qs[(m + gid    ) * QKW + kb + tig + 4];
                af[mt][3] = Qs[(m + gid + 8) * QKW + kb + tig + 4];
            }
            uint32_t bf[4][2];
            #pragma unroll
            for (int nt = 0; nt < 4; nt++) {
                int n = wn * 32 + nt * 8;
                bf[nt][0] = Rs[(n + gid) * QKW + kb + tig    ];
                bf[nt][1] = Rs[(n + gid) * QKW + kb + tig + 4];
            }
            #pragma unroll
            for (int mt = 0; mt < 4; mt++)
                #pragma unroll
                for (int nt = 0; nt < 4; nt++)
                    mma_f16(acc2[mt][nt], af[mt], bf[nt]);
        }
        #pragma unroll
        for (int mt = 0; mt < 4; mt++) {
            #pragma unroll
            for (int nt = 0; nt < 4; nt++) {
                int m0 = row0 + wm * 64 + mt * 16 + gid;
                int n  = wn * 32 + nt * 8 + tig * 2;
                *(float2*)&g_qrel[((size_t)bh * SS + m0) * NREL_ + n] =
                    make_float2(acc2[mt][nt][0], acc2[mt][nt][1]);
                *(float2*)&g_qrel[((size_t)bh * SS + m0 + 8) * NREL_ + n] =
                    make_float2(acc2[mt][nt][2], acc2[mt][nt][3]);
            }
        }
    }

    float acc[4][4][4] = {};
    #pragma unroll
    for (int ks = 0; ks < 4; ks++) {
        int kb = ks * 8;
        uint32_t af[4][4];
        #pragma unroll
        for (int mt = 0; mt < 4; mt++) {
            int m = wm * 64 + mt * 16;
            af[mt][0] = Qs[(m + gid    ) * QKW + kb + tig    ];
            af[mt][1] = Qs[(m + gid + 8) * QKW + kb + tig    ];
            af[mt][2] = Qs[(m + gid    ) * QKW + kb + tig + 4];
            af[mt][3] = Qs[(m + gid + 8) * QKW + kb + tig + 4];
        }
        uint32_t bf[4][2];
        #pragma unroll
        for (int nt = 0; nt < 4; nt++) {
            int n = wn * 32 + nt * 8;
            bf[nt][0] = Ks[(n + gid) * QKW + kb + tig    ];
            bf[nt][1] = Ks[(n + gid) * QKW + kb + tig + 4];
        }
        #pragma unroll
        for (int mt = 0; mt < 4; mt++)
            #pragma unroll
            for (int nt = 0; nt < 4; nt++)
                mma_f16(acc[mt][nt], af[mt], bf[nt]);
    }

    uint32_t* Og = g_s16 + (size_t)bh * SS * (SS / 2);
    #pragma unroll
    for (int mt = 0; mt < 4; mt++) {
        #pragma unroll
        for (int nt = 0; nt < 4; nt++) {
            int m0 = row0 + wm * 64 + mt * 16 + gid;
            int n  = col0 + wn * 32 + nt * 8 + tig * 2;
            Og[((size_t)m0 * SS + n) >> 1] =
                pack_h16(acc[mt][nt][0], acc[mt][nt][1]);
            Og[((size_t)(m0 + 8) * SS + n) >> 1] =
                pack_h16(acc[mt][nt][2], acc[mt][nt][3]);
        }
    }
}

// ===== softmax: warp per row, single pass (no max), fp16 in / fp16 out =======
__global__ void __launch_bounds__(256)
softmax_kernel(const int* __restrict__ mask)
{
    __shared__ float qtab[8][64];
    __shared__ float bins[8][64];

    int tid  = threadIdx.x;
    int lane = tid & 31;
    int wid  = tid >> 5;

    int rowg = blockIdx.x * 8 + wid;      // bh*512 + q
    int bh = rowg >> 9;
    int q  = rowg & 511;
    int b  = bh >> 4;

    qtab[wid][lane]      = g_qrel[(size_t)rowg * NREL_ + lane]      * 0.03125f;
    qtab[wid][lane + 32] = g_qrel[(size_t)rowg * NREL_ + lane + 32] * 0.03125f;
    bins[wid][lane]      = 0.f;
    bins[wid][lane + 32] = 0.f;
    __syncwarp();

    const uint4* srow = (const uint4*)(g_s16 + (size_t)rowg * (SS / 2));
    const int4*  mrow = (const int4*)(mask + ((size_t)b * SS + q) * SS);
    uint4*       prow = (uint4*)(g_p16 + (size_t)rowg * (SS / 2));

    float p[16];
    int   ids[16];
    float sum = 0.f;

    #pragma unroll
    for (int hlf = 0; hlf < 2; hlf++) {
        uint4 sv = srow[lane + 32 * hlf];          // 8 fp16 scores
        int4  ia = mrow[2 * lane + 64 * hlf];
        int4  ib = mrow[2 * lane + 64 * hlf + 1];
        float fs[8];
        {
            __half2 t;
            float2 f;
            t = *(__half2*)&sv.x; f = __half22float2(t); fs[0]=f.x; fs[1]=f.y;
            t = *(__half2*)&sv.y; f = __half22float2(t); fs[2]=f.x; fs[3]=f.y;
            t = *(__half2*)&sv.z; f = __half22float2(t); fs[4]=f.x; fs[5]=f.y;
            t = *(__half2*)&sv.w; f = __half22float2(t); fs[6]=f.x; fs[7]=f.y;
        }
        int idv[8] = {ia.x, ia.y, ia.z, ia.w, ib.x, ib.y, ib.z, ib.w};
        #pragma unroll
        for (int j = 0; j < 8; j++) {
            int k = hlf * 8 + j;
            int id = idv[j];
            float v = (id > 0)
                ? __expf(fmaf(fs[j], 0.125f, qtab[wid][id])) : 0.f;
            p[k] = v;
            ids[k] = id;
            sum += v;
        }
    }
    #pragma unroll
    for (int o = 16; o; o >>= 1) sum += __shfl_xor_sync(0xffffffffu, sum, o);
    float inv = 1.f / sum;

    #pragma unroll
    for (int hlf = 0; hlf < 2; hlf++) {
        int k = hlf * 8;
        uint4 o;
        o.x = pack_h16(p[k+0] * inv, p[k+1] * inv);
        o.y = pack_h16(p[k+2] * inv, p[k+3] * inv);
        o.z = pack_h16(p[k+4] * inv, p[k+5] * inv);
        o.w = pack_h16(p[k+6] * inv, p[k+7] * inv);
        prow[lane + 32 * hlf] = o;
    }
    #pragma unroll
    for (int k = 0; k < 16; k++)
        atomicAdd(&bins[wid][ids[k]], p[k]);
    __syncwarp();

    float sc = 0.25f * inv;
    g_pr16[(size_t)rowg * (NREL_ / 2) + lane] =
        pack_h16(sc * bins[wid][2 * lane], sc * bins[wid][2 * lane + 1]);
}

// ========== av: out = probs @ V + pr' @ rel_v (fp16 MMA, 64-row tiles) =======
#define AVW 36
#define AVPT (64 * AVW)      // P tile words per stage
#define AVVT (64 * AVW)      // V tile words per stage
#define AVST (AVPT + AVVT)

__global__ void __launch_bounds__(256)
av_kernel()
{
    extern __shared__ uint32_t sm3[];   // [2][Ps 64x36 | Vs 64x36]

    int tid  = threadIdx.x;
    int lane = tid & 31;
    int wid  = tid >> 5;
    int wm   = wid & 1;        // 2 warps over 64 rows (32 each)
    int wn   = wid >> 1;       // 4 warps over 64 cols (16 each)
    int gid  = lane >> 2;
    int tig  = lane & 3;

    int bh = blockIdx.y;
    int q0 = blockIdx.x * 64;
    int b  = bh >> 4, h = bh & 15;

    uint32_t smem_base = smem_u32(sm3);

    const __half* Pg  = (const __half*)g_p16 + (size_t)bh * SS * SS;
    const __half* PRg = (const __half*)g_pr16 + ((size_t)bh * SS + q0) * NREL_;
    const __half* Vg  = g_Vh + (size_t)bh * SS * DD;   // [d][s]

    auto issue = [&](int st, int kt) {
        uint32_t ps = smem_base + (st * AVST) * 4;
        uint32_t vs = ps + AVPT * 4;
        if (kt < 8) {
            #pragma unroll
            for (int p = 0; p < 2; p++) {
                int ch = tid + p * 256;        // 0..511
                int r = ch >> 3, cq = ch & 7;
                cp_async16(ps + (r * AVW + cq * 4) * 4,
                           Pg + (size_t)(q0 + r) * SS + kt * 64 + cq * 8);
            }
            #pragma unroll
            for (int p = 0; p < 2; p++) {
                int ch = tid + p * 256;        // 0..511
                int r = ch >> 3, cq = ch & 7;
                cp_async16(vs + (r * AVW + cq * 4) * 4,
                           Vg + (size_t)r * SS + kt * 64 + cq * 8);
            }
        } else {
            #pragma unroll
            for (int p = 0; p < 2; p++) {
                int ch = tid + p * 256;
                int r = ch >> 3, cq = ch & 7;
                cp_async16(ps + (r * AVW + cq * 4) * 4,
                           PRg + (size_t)r * NREL_ + cq * 8);
            }
            // rel_v transposed: Vs word[d][w] = {relv[2w][d], relv[2w+1][d]}
            uint32_t* vsp = sm3 + st * AVST + AVPT;
            #pragma unroll
            for (int p = 0; p < 8; p++) {
                int idx = tid + p * 256;       // 0..2047
                int d = idx >> 5, w = idx & 31;
                float v0 = __half2float(g_relv_h[(size_t)(2 * w) * DD + d]);
                float v1 = __half2float(g_relv_h[(size_t)(2 * w + 1) * DD + d]);
                vsp[d * AVW + w] = pack_h16(v0, v1);
            }
        }
    };

    float acc[2][4] = {};
    float acc2[2][4] = {};

    issue(0, 0);
    asm volatile("cp.async.commit_group;\n" ::);

    for (int kt = 0; kt < 9; kt++) {
        if (kt + 1 < 9) {
            issue((kt + 1) & 1, kt + 1);
            asm volatile("cp.async.commit_group;\n" ::);
            asm volatile("cp.async.wait_group 1;\n" ::);
        } else {
            asm volatile("cp.async.wait_group 0;\n" ::);
        }
        __syncthreads();

        const uint32_t* Ps = sm3 + (kt & 1) * AVST;
        const uint32_t* Vs = Ps + AVPT;

        #pragma unroll
        for (int ks = 0; ks < 4; ks++) {
            int kb = ks * 8;
            uint32_t af[2][4];
            #pragma unroll
            for (int mt = 0; mt < 2; mt++) {
                int m = wm * 32 + mt * 16;
                af[mt][0] = Ps[(m + gid    ) * AVW + kb + tig    ];
                af[mt][1] = Ps[(m + gid + 8) * AVW + kb + tig    ];
                af[mt][2] = Ps[(m + gid    ) * AVW + kb + tig + 4];
                af[mt][3] = Ps[(m + gid + 8) * AVW + kb + tig + 4];
            }
            uint32_t bf0[2], bf1[2];
            int n0 = wn * 16;
            bf0[0] = Vs[(n0 + gid    ) * AVW + kb + tig    ];
            bf0[1] = Vs[(n0 + gid    ) * AVW + kb + tig + 4];
            bf1[0] = Vs[(n0 + 8 + gid) * AVW + kb + tig    ];
            bf1[1] = Vs[(n0 + 8 + gid) * AVW + kb + tig + 4];
            #pragma unroll
            for (int mt = 0; mt < 2; mt++) {
                mma_f16(acc[mt],  af[mt], bf0);
                mma_f16(acc2[mt], af[mt], bf1);
            }
        }
        __syncthreads();
    }

    #pragma unroll
    for (int mt = 0; mt < 2; mt++) {
        int qa = q0 + wm * 32 + mt * 16 + gid;
        int n0 = wn * 16 + tig * 2;
        size_t w0 = (((size_t)b * SS + qa    ) * HID_ + h * DD + n0) >> 1;
        size_t w1 = (((size_t)b * SS + qa + 8) * HID_ + h * DD + n0) >> 1;
        g_attn16[w0]     = pack_h16(acc[mt][0],  acc[mt][1]);
        g_attn16[w0 + 4] = pack_h16(acc2[mt][0], acc2[mt][1]);
        g_attn16[w1]     = pack_h16(acc[mt][2],  acc[mt][3]);
        g_attn16[w1 + 4] = pack_h16(acc2[mt][2], acc2[mt][3]);
    }
}

// ---------------- launch -----------------------------------------------------
extern "C" void kernel_launch(void* const* d_in, const int* in_sizes, int n_in,
                              void* d_out, int out_size)
{
    const float* q_in = (const float*)d_in[0];
    const float* k_in = (const float*)d_in[1];
    const float* v_in = (const float*)d_in[2];
    const int*   mask = (const int*)  d_in[3];
    const float* Wq   = (const float*)d_in[4];
    const float* bq   = (const float*)d_in[5];
    const float* Wk   = (const float*)d_in[6];
    const float* bk   = (const float*)d_in[7];
    const float* Wv   = (const float*)d_in[8];
    const float* bv   = (const float*)d_in[9];
    const float* Wo   = (const float*)d_in[10];
    const float* bo   = (const float*)d_in[11];
    const float* relk = (const float*)d_in[12];
    const float* relv = (const float*)d_in[13];
    float* out = (float*)d_out;

    void *pQ, *pK, *pV, *pAttn;
    void *pRq, *pRk, *pRv, *pWq, *pWk, *pWv, *pWo, *pRelk, *pRelv;
    cudaGetSymbolAddress(&pQ,    g_Qh);
    cudaGetSymbolAddress(&pK,    g_Kh);
    cudaGetSymbolAddress(&pV,    g_Vh);
    cudaGetSymbolAddress(&pAttn, g_attn16);
    cudaGetSymbolAddress(&pRq,   g_rq);
    cudaGetSymbolAddress(&pRk,   g_rk);
    cudaGetSymbolAddress(&pRv,   g_rv);
    cudaGetSymbolAddress(&pWq,   g_wq);
    cudaGetSymbolAddress(&pWk,   g_wk);
    cudaGetSymbolAddress(&pWv,   g_wv);
    cudaGetSymbolAddress(&pWo,   g_wo);
    cudaGetSymbolAddress(&pRelk, g_relk_h);
    cudaGetSymbolAddress(&pRelv, g_relv_h);

    // 1) fp32 -> fp16 conversion of all GEMM inputs + rel tables
    RoundArgs ra;
    ra.src[0] = (const float4*)q_in; ra.dst[0] = (uint2*)pRq; ra.n4[0] = TT*HID_/4;
    ra.src[1] = (const float4*)k_in; ra.dst[1] = (uint2*)pRk; ra.n4[1] = TT*HID_/4;
    ra.src[2] = (const float4*)v_in; ra.dst[2] = (uint2*)pRv; ra.n4[2] = TT*HID_/4;
    ra.src[3] = (const float4*)Wq;   ra.dst[3] = (uint2*)pWq; ra.n4[3] = HID_*HID_/4;
    ra.src[4] = (const float4*)Wk;   ra.dst[4] = (uint2*)pWk; ra.n4[4] = HID_*HID_/4;
    ra.src[5] = (const float4*)Wv;   ra.dst[5] = (uint2*)pWv; ra.n4[5] = HID_*HID_/4;
    ra.src[6] = (const float4*)Wo;   ra.dst[6] = (uint2*)pWo; ra.n4[6] = HID_*HID_/4;
    ra.src[7] = (const float4*)relk; ra.dst[7] = (uint2*)pRelk; ra.n4[7] = NREL_*DD/4;
    ra.src[8] = (const float4*)relv; ra.dst[8] = (uint2*)pRelv; ra.n4[8] = NREL_*DD/4;
    round_f16_kernel<<<dim3(512, 9), 256>>>(ra);

    const int gemmSmem = 2 * 2 * GTILE * 4;   // 73728 B (proven 2 CTA/SM)
    cudaFuncSetAttribute(h16_gemm_kernel,
                         cudaFuncAttributeMaxDynamicSharedMemorySize, gemmSmem);

    // 2) fused QKV projection (V stored transposed per head)
    GemmArgs qkv;
    qkv.X[0] = (const __half*)pRq; qkv.X[1] = (const __half*)pRk; qkv.X[2] = (const __half*)pRv;
    qkv.W[0] = (const __half*)pWq; qkv.W[1] = (const __half*)pWk; qkv.W[2] = (const __half*)pWv;
    qkv.b[0] = bq;  qkv.b[1] = bk;  qkv.b[2] = bv;
    qkv.O[0] = pQ;  qkv.O[1] = pK;  qkv.O[2] = pV;
    qkv.sc[0] = 1;  qkv.sc[1] = 1;  qkv.sc[2] = 2;
    h16_gemm_kernel<<<dim3(HID_ / GBM, TT / GBM, 3), 256, gemmSmem>>>(qkv);

    // 3) scores = Q @ K^T (+ fused qrel), fp16 out
    const int qkSmem = (256 * QKW + 64 * QKW) * 4;   // 46080 B
    cudaFuncSetAttribute(qk_scores_kernel,
                         cudaFuncAttributeMaxDynamicSharedMemorySize, qkSmem);
    qk_scores_kernel<<<dim3(4, 4, BH), 256, qkSmem>>>();

    // 4) softmax + relation bins
    softmax_kernel<<<BH * SS / 8, 256>>>(mask);

    // 5) AV + relation-V (fp16 MMA, 64-row tiles for occupancy)
    const int avSmem = 2 * AVST * 4;                 // 36864 B
    cudaFuncSetAttribute(av_kernel,
                         cudaFuncAttributeMaxDynamicSharedMemorySize, avSmem);
    av_kernel<<<dim3(8, BH), 256, avSmem>>>();

    // 6) output projection (fp32 out)
    GemmArgs og;
    og.X[0] = (const __half*)pAttn; og.W[0] = (const __half*)pWo;
    og.b[0] = bo; og.O[0] = out;
    og.X[1] = og.X[2] = nullptr; og.W[1] = og.W[2] = nullptr;
    og.b[1] = og.b[2] = nullptr; og.O[1] = og.O[2] = nullptr;
    og.sc[0] = 0; og.sc[1] = 0; og.sc[2] = 0;
    h16_gemm_kernel<<<dim3(HID_ / GBM, TT / GBM, 1), 256, gemmSmem>>>(og);
}

// round 16
// speedup vs baseline: 1.1647x; 1.0768x over previous
#include <cuda_runtime.h>
#include <cuda_bf16.h>
#include <cuda_fp16.h>
#include <math.h>
#include <stdint.h>

#define BB   4
#define SS   512
#define HID_ 1024
#define HH   16
#define DD   64
#define NREL_ 64
#define TT   (BB*SS)      // 2048 tokens
#define BH   (BB*HH)      // 64

// ---------------- scratch (static device globals; fp16 packed in uint32) ----
__device__ uint32_t g_Qh[BH*SS*DD/2];             // [bh][s][d] fp16
__device__ uint32_t g_Kh[BH*SS*DD/2];             // [bh][s][d] fp16
__device__ __half   g_Vh[BH*SS*DD];               // [bh][d][s] fp16 (TRANSPOSED)
__device__ float    g_qrel[BH*SS*NREL_];          // fp32
__device__ uint32_t g_pr16[BH*SS*NREL_/2];        // 0.25-scaled, fp16
__device__ uint32_t g_s16[(size_t)BH*SS*SS/2];    // raw scores fp16 (32 MB)
__device__ uint32_t g_p16[(size_t)BH*SS*SS/2];    // probs fp16 (32 MB)
__device__ uint32_t g_attn16[TT*HID_/2];          // attention output fp16
// fp16 copies of GEMM inputs + rel tables
__device__ uint32_t g_rq[TT*HID_/2];
__device__ uint32_t g_rk[TT*HID_/2];
__device__ uint32_t g_rv[TT*HID_/2];
__device__ uint32_t g_wq[HID_*HID_/2];
__device__ uint32_t g_wk[HID_*HID_/2];
__device__ uint32_t g_wv[HID_*HID_/2];
__device__ uint32_t g_wo[HID_*HID_/2];
__device__ uint32_t g_relk_h[NREL_*DD/2];
__device__ __half   g_relv_h[NREL_*DD];

__device__ __forceinline__ uint32_t pack_h16(float a, float b) {
    __half2 t = __floats2half2_rn(a, b);
    return *(uint32_t*)&t;
}

// ---------------- fp32 -> fp16 conversion pass -------------------------------
struct RoundArgs {
    const float4* src[9];
    uint2*        dst[9];
    int           n4[9];
};
__global__ void round_f16_kernel(RoundArgs a)
{
    int seg = blockIdx.y;
    const float4* s = a.src[seg];
    uint2*        d = a.dst[seg];
    int n = a.n4[seg];
    for (int i = blockIdx.x * blockDim.x + threadIdx.x; i < n;
         i += gridDim.x * blockDim.x) {
        float4 v = s[i];
        uint2 o;
        o.x = pack_h16(v.x, v.y);
        o.y = pack_h16(v.z, v.w);
        d[i] = o;
    }
}

// ======================= MMA / cp.async / ldmatrix helpers ===================
__device__ __forceinline__ void mma_f16(float c[4], const uint32_t a[4],
                                        const uint32_t b2[2]) {
    asm volatile(
        "mma.sync.aligned.m16n8k16.row.col.f32.f16.f16.f32 "
        "{%0,%1,%2,%3}, {%4,%5,%6,%7}, {%8,%9}, {%0,%1,%2,%3};"
        : "+f"(c[0]), "+f"(c[1]), "+f"(c[2]), "+f"(c[3])
        : "r"(a[0]), "r"(a[1]), "r"(a[2]), "r"(a[3]),
          "r"(b2[0]), "r"(b2[1]));
}
__device__ __forceinline__ void cp_async16(uint32_t smem, const void* g) {
    asm volatile("cp.async.cg.shared.global [%0], [%1], 16;\n"
                 :: "r"(smem), "l"(g));
}
__device__ __forceinline__ uint32_t smem_u32(const void* p) {
    return (uint32_t)__cvta_generic_to_shared(p);
}
__device__ __forceinline__ void ldmx4(uint32_t* r, uint32_t a) {
    asm volatile("ldmatrix.sync.aligned.m8n8.x4.shared.b16 {%0,%1,%2,%3}, [%4];"
        : "=r"(r[0]), "=r"(r[1]), "=r"(r[2]), "=r"(r[3]) : "r"(a));
}

// ======================= fp16 tensor-core GEMM (2-stage, GBK=64) =============
struct GemmArgs {
    const __half* X[3];
    const __half* W[3];
    const float*  b[3];
    void*         O[3];
    int sc[3];
};

#define GBM 128
#define GBK 64                 // halfs per k-tile
#define GLDW 36                // uint32 per smem row (32 data + 4 pad)
#define GTILE (GBM * GLDW)     // words per matrix per stage

__global__ void __launch_bounds__(256, 2)
h16_gemm_kernel(GemmArgs args)
{
    const int K = 1024, N = 1024;
    int mat = blockIdx.z;
    const __half* __restrict__ X    = args.X[mat];
    const __half* __restrict__ W    = args.W[mat];
    const float*  __restrict__ bias = args.b[mat];
    void*                      O    = args.O[mat];
    int sc = args.sc[mat];

    extern __shared__ uint32_t smg[];   // [2 stages][2 mats][128][36]

    int tid  = threadIdx.x;
    int lane = tid & 31;
    int wid  = tid >> 5;
    int wm   = wid & 1;
    int wn   = wid >> 1;
    int gid  = lane >> 2;
    int tig  = lane & 3;

    // ldmatrix address lanes
    int rA = lane & 15;
    int kA = (lane >> 4) * 4;
    int rB = (lane & 7) + ((lane >> 1) & 8);
    int kB = (lane >> 1) & 4;

    int row0 = blockIdx.y * GBM;
    int col0 = blockIdx.x * GBM;

    uint32_t smem_base = smem_u32(smg);

    float acc[4][4][4] = {};
    const int KT = K / GBK;   // 16

    auto issue = [&](int st, int k0) {
        uint32_t xs = smem_base + (st * 2 * GTILE) * 4;
        uint32_t ws = xs + GTILE * 4;
        #pragma unroll
        for (int p = 0; p < 4; p++) {
            int ch = tid + p * 256;        // 0..1023
            int r = ch >> 3, cq = ch & 7;  // 8 chunks of 8 halfs per row
            cp_async16(xs + (r * GLDW + cq * 4) * 4,
                       X + (size_t)(row0 + r) * K + k0 + cq * 8);
            cp_async16(ws + (r * GLDW + cq * 4) * 4,
                       W + (size_t)(col0 + r) * K + k0 + cq * 8);
        }
    };

    issue(0, 0);
    asm volatile("cp.async.commit_group;\n" ::);

    for (int kt = 0; kt < KT; kt++) {
        if (kt + 1 < KT) {
            issue((kt + 1) & 1, (kt + 1) * GBK);
            asm volatile("cp.async.commit_group;\n" ::);
            asm volatile("cp.async.wait_group 1;\n" ::);
        } else {
            asm volatile("cp.async.wait_group 0;\n" ::);
        }
        __syncthreads();

        uint32_t xb = smem_base + ((kt & 1) * 2 * GTILE) * 4;
        uint32_t wb = xb + GTILE * 4;

        #pragma unroll
        for (int ks = 0; ks < 4; ks++) {
            int kb = ks * 8;
            uint32_t af[4][4];
            #pragma unroll
            for (int mt = 0; mt < 4; mt++) {
                int m = wm * 64 + mt * 16;
                ldmx4(af[mt], xb + ((m + rA) * GLDW + kb + kA) * 4);
            }
            uint32_t bt[2][4];
            ldmx4(bt[0], wb + ((wn * 32 + rB) * GLDW + kb + kB) * 4);
            ldmx4(bt[1], wb + ((wn * 32 + 16 + rB) * GLDW + kb + kB) * 4);
            #pragma unroll
            for (int mt = 0; mt < 4; mt++) {
                mma_f16(acc[mt][0], af[mt], &bt[0][0]);
                mma_f16(acc[mt][1], af[mt], &bt[0][2]);
                mma_f16(acc[mt][2], af[mt], &bt[1][0]);
                mma_f16(acc[mt][3], af[mt], &bt[1][2]);
            }
        }
        __syncthreads();
    }

    #pragma unroll
    for (int mt = 0; mt < 4; mt++) {
        #pragma unroll
        for (int nt = 0; nt < 4; nt++) {
            int m = row0 + wm * 64 + mt * 16 + gid;
            int n = col0 + wn * 32 + nt * 8 + tig * 2;
            float y00 = acc[mt][nt][0] + bias[n];
            float y01 = acc[mt][nt][1] + bias[n + 1];
            float y10 = acc[mt][nt][2] + bias[n];
            float y11 = acc[mt][nt][3] + bias[n + 1];
            if (sc == 1) {
                uint32_t* Oh = (uint32_t*)O;
                int b = m >> 9, s = m & 511, h = n >> 6, d = n & 63;
                Oh[((((size_t)b * HH + h) * SS + s) * DD + d) >> 1] =
                    pack_h16(y00, y01);
                int s2 = (m + 8) & 511;
                Oh[((((size_t)b * HH + h) * SS + s2) * DD + d) >> 1] =
                    pack_h16(y10, y11);
            } else if (sc == 2) {
                __half* Oh = (__half*)O;
                int b = m >> 9, s = m & 511, h = n >> 6, d = n & 63;
                size_t base = (((size_t)b * HH + h) * DD + d) * SS;
                Oh[base + s]           = __float2half(y00);
                Oh[base + SS + s]      = __float2half(y01);
                Oh[base + s + 8]       = __float2half(y10);
                Oh[base + SS + s + 8]  = __float2half(y11);
            } else {
                float* Of = (float*)O;
                *(float2*)&Of[(size_t)m * N + n]       = make_float2(y00, y01);
                *(float2*)&Of[(size_t)(m + 8) * N + n] = make_float2(y10, y11);
            }
        }
    }
}

// ================= qk_scores (+fused qrel): fp16 MMA, ldmatrix ==============
#define QKW 36    // uint32 per smem row (32 data + 4 pad)

__global__ void __launch_bounds__(256, 2)
qk_scores_kernel()
{
    extern __shared__ uint32_t sm2[];   // Qs[128][36] Ks[128][36] Rs[64][36]
    uint32_t* Qs = sm2;
    uint32_t* Ks = sm2 + 128 * QKW;
    uint32_t* Rs = sm2 + 256 * QKW;

    int tid  = threadIdx.x;
    int lane = tid & 31;
    int wid  = tid >> 5;
    int wm   = wid & 1;
    int wn   = wid >> 1;
    int gid  = lane >> 2;
    int tig  = lane & 3;

    int rA = lane & 15;
    int kA = (lane >> 4) * 4;
    int rB = (lane & 7) + ((lane >> 1) & 8);
    int kB = (lane >> 1) & 4;

    int bh   = blockIdx.z;
    int row0 = blockIdx.y * 128;
    int col0 = blockIdx.x * 128;

    const __half* Qg = (const __half*)g_Qh + (size_t)bh * SS * DD;
    const __half* Kg = (const __half*)g_Kh + (size_t)bh * SS * DD;

    uint32_t qs0 = smem_u32(Qs);
    uint32_t ks0 = smem_u32(Ks);
    uint32_t rs0 = smem_u32(Rs);

    #pragma unroll
    for (int p = 0; p < 4; p++) {
        int ch = tid + p * 256;
        int r = ch >> 3, cq = ch & 7;
        cp_async16(qs0 + (r * QKW + cq * 4) * 4,
                   Qg + (size_t)(row0 + r) * DD + cq * 8);
        cp_async16(ks0 + (r * QKW + cq * 4) * 4,
                   Kg + (size_t)(col0 + r) * DD + cq * 8);
    }
    if (col0 == 0) {
        #pragma unroll
        for (int p = 0; p < 2; p++) {
            int ch = tid + p * 256;
            int r = ch >> 3, cq = ch & 7;
            cp_async16(rs0 + (r * QKW + cq * 4) * 4,
                       (const __half*)g_relk_h + (size_t)r * DD + cq * 8);
        }
    }
    asm volatile("cp.async.commit_group;\n" ::);
    asm volatile("cp.async.wait_group 0;\n" ::);
    __syncthreads();

    // fused qrel (only first n-tile; warps wn<2 cover the 64 rel columns)
    if (col0 == 0 && wn < 2) {
        float acc2[4][4][4] = {};
        #pragma unroll
        for (int ks = 0; ks < 4; ks++) {
            int kb = ks * 8;
            uint32_t af[4][4];
            #pragma unroll
            for (int mt = 0; mt < 4; mt++) {
                int m = wm * 64 + mt * 16;
                ldmx4(af[mt], qs0 + ((m + rA) * QKW + kb + kA) * 4);
            }
            uint32_t bt[2][4];
            ldmx4(bt[0], rs0 + ((wn * 32 + rB) * QKW + kb + kB) * 4);
            ldmx4(bt[1], rs0 + ((wn * 32 + 16 + rB) * QKW + kb + kB) * 4);
            #pragma unroll
            for (int mt = 0; mt < 4; mt++) {
                mma_f16(acc2[mt][0], af[mt], &bt[0][0]);
                mma_f16(acc2[mt][1], af[mt], &bt[0][2]);
                mma_f16(acc2[mt][2], af[mt], &bt[1][0]);
                mma_f16(acc2[mt][3], af[mt], &bt[1][2]);
            }
        }
        #pragma unroll
        for (int mt = 0; mt < 4; mt++) {
            #pragma unroll
            for (int nt = 0; nt < 4; nt++) {
                int m0 = row0 + wm * 64 + mt * 16 + gid;
                int n  = wn * 32 + nt * 8 + tig * 2;
                *(float2*)&g_qrel[((size_t)bh * SS + m0) * NREL_ + n] =
                    make_float2(acc2[mt][nt][0], acc2[mt][nt][1]);
                *(float2*)&g_qrel[((size_t)bh * SS + m0 + 8) * NREL_ + n] =
                    make_float2(acc2[mt][nt][2], acc2[mt][nt][3]);
            }
        }
    }

    float acc[4][4][4] = {};
    #pragma unroll
    for (int ks = 0; ks < 4; ks++) {
        int kb = ks * 8;
        uint32_t af[4][4];
        #pragma unroll
        for (int mt = 0; mt < 4; mt++) {
            int m = wm * 64 + mt * 16;
            ldmx4(af[mt], qs0 + ((m + rA) * QKW + kb + kA) * 4);
        }
        uint32_t bt[2][4];
        ldmx4(bt[0], ks0 + ((wn * 32 + rB) * QKW + kb + kB) * 4);
        ldmx4(bt[1], ks0 + ((wn * 32 + 16 + rB) * QKW + kb + kB) * 4);
        #pragma unroll
        for (int mt = 0; mt < 4; mt++) {
            mma_f16(acc[mt][0], af[mt], &bt[0][0]);
            mma_f16(acc[mt][1], af[mt], &bt[0][2]);
            mma_f16(acc[mt][2], af[mt], &bt[1][0]);
            mma_f16(acc[mt][3], af[mt], &bt[1][2]);
        }
    }

    uint32_t* Og = g_s16 + (size_t)bh * SS * (SS / 2);
    #pragma unroll
    for (int mt = 0; mt < 4; mt++) {
        #pragma unroll
        for (int nt = 0; nt < 4; nt++) {
            int m0 = row0 + wm * 64 + mt * 16 + gid;
            int n  = col0 + wn * 32 + nt * 8 + tig * 2;
            Og[((size_t)m0 * SS + n) >> 1] =
                pack_h16(acc[mt][nt][0], acc[mt][nt][1]);
            Og[((size_t)(m0 + 8) * SS + n) >> 1] =
                pack_h16(acc[mt][nt][2], acc[mt][nt][3]);
        }
    }
}

// ===== softmax: warp per row, single pass (no max), fp16 in / fp16 out =======
__global__ void __launch_bounds__(256)
softmax_kernel(const int* __restrict__ mask)
{
    __shared__ float qtab[8][64];
    __shared__ float bins[8][64];

    int tid  = threadIdx.x;
    int lane = tid & 31;
    int wid  = tid >> 5;

    int rowg = blockIdx.x * 8 + wid;      // bh*512 + q
    int bh = rowg >> 9;
    int q  = rowg & 511;
    int b  = bh >> 4;

    qtab[wid][lane]      = g_qrel[(size_t)rowg * NREL_ + lane]      * 0.03125f;
    qtab[wid][lane + 32] = g_qrel[(size_t)rowg * NREL_ + lane + 32] * 0.03125f;
    bins[wid][lane]      = 0.f;
    bins[wid][lane + 32] = 0.f;
    __syncwarp();

    const uint4* srow = (const uint4*)(g_s16 + (size_t)rowg * (SS / 2));
    const int4*  mrow = (const int4*)(mask + ((size_t)b * SS + q) * SS);
    uint4*       prow = (uint4*)(g_p16 + (size_t)rowg * (SS / 2));

    float p[16];
    int   ids[16];
    float sum = 0.f;

    #pragma unroll
    for (int hlf = 0; hlf < 2; hlf++) {
        uint4 sv = srow[lane + 32 * hlf];          // 8 fp16 scores
        int4  ia = mrow[2 * lane + 64 * hlf];
        int4  ib = mrow[2 * lane + 64 * hlf + 1];
        float fs[8];
        {
            __half2 t;
            float2 f;
            t = *(__half2*)&sv.x; f = __half22float2(t); fs[0]=f.x; fs[1]=f.y;
            t = *(__half2*)&sv.y; f = __half22float2(t); fs[2]=f.x; fs[3]=f.y;
            t = *(__half2*)&sv.z; f = __half22float2(t); fs[4]=f.x; fs[5]=f.y;
            t = *(__half2*)&sv.w; f = __half22float2(t); fs[6]=f.x; fs[7]=f.y;
        }
        int idv[8] = {ia.x, ia.y, ia.z, ia.w, ib.x, ib.y, ib.z, ib.w};
        #pragma unroll
        for (int j = 0; j < 8; j++) {
            int k = hlf * 8 + j;
            int id = idv[j];
            float v = (id > 0)
                ? __expf(fmaf(fs[j], 0.125f, qtab[wid][id])) : 0.f;
            p[k] = v;
            ids[k] = id;
            sum += v;
        }
    }
    #pragma unroll
    for (int o = 16; o; o >>= 1) sum += __shfl_xor_sync(0xffffffffu, sum, o);
    float inv = 1.f / sum;

    #pragma unroll
    for (int hlf = 0; hlf < 2; hlf++) {
        int k = hlf * 8;
        uint4 o;
        o.x = pack_h16(p[k+0] * inv, p[k+1] * inv);
        o.y = pack_h16(p[k+2] * inv, p[k+3] * inv);
        o.z = pack_h16(p[k+4] * inv, p[k+5] * inv);
        o.w = pack_h16(p[k+6] * inv, p[k+7] * inv);
        prow[lane + 32 * hlf] = o;
    }
    #pragma unroll
    for (int k = 0; k < 16; k++)
        atomicAdd(&bins[wid][ids[k]], p[k]);
    __syncwarp();

    float sc = 0.25f * inv;
    g_pr16[(size_t)rowg * (NREL_ / 2) + lane] =
        pack_h16(sc * bins[wid][2 * lane], sc * bins[wid][2 * lane + 1]);
}

// ===== av: out = probs @ V + pr' @ rel_v (fp16 MMA, 128-row, ldmatrix) ======
#define AVW 36
#define AVPT (128 * AVW)     // P tile words per stage
#define AVVT (64 * AVW)      // V tile words per stage
#define AVST (AVPT + AVVT)

__global__ void __launch_bounds__(256)
av_kernel()
{
    extern __shared__ uint32_t sm3[];   // [2][Ps 128x36 | Vs 64x36]

    int tid  = threadIdx.x;
    int lane = tid & 31;
    int wid  = tid >> 5;
    int wm   = wid & 1;
    int wn   = wid >> 1;
    int gid  = lane >> 2;
    int tig  = lane & 3;

    int rA = lane & 15;
    int kA = (lane >> 4) * 4;
    int rB = (lane & 7) + ((lane >> 1) & 8);
    int kB = (lane >> 1) & 4;

    int bh = blockIdx.y;
    int q0 = blockIdx.x * 128;
    int b  = bh >> 4, h = bh & 15;

    uint32_t smem_base = smem_u32(sm3);

    const __half* Pg  = (const __half*)g_p16 + (size_t)bh * SS * SS;
    const __half* PRg = (const __half*)g_pr16 + ((size_t)bh * SS + q0) * NREL_;
    const __half* Vg  = g_Vh + (size_t)bh * SS * DD;   // [d][s]

    auto issue = [&](int st, int kt) {
        uint32_t ps = smem_base + (st * AVST) * 4;
        uint32_t vs = ps + AVPT * 4;
        if (kt < 8) {
            #pragma unroll
            for (int p = 0; p < 4; p++) {
                int ch = tid + p * 256;        // 0..1023
                int r = ch >> 3, cq = ch & 7;
                cp_async16(ps + (r * AVW + cq * 4) * 4,
                           Pg + (size_t)(q0 + r) * SS + kt * 64 + cq * 8);
            }
            #pragma unroll
            for (int p = 0; p < 2; p++) {
                int ch = tid + p * 256;        // 0..511
                int r = ch >> 3, cq = ch & 7;
                cp_async16(vs + (r * AVW + cq * 4) * 4,
                           Vg + (size_t)r * SS + kt * 64 + cq * 8);
            }
        } else {
            #pragma unroll
            for (int p = 0; p < 4; p++) {
                int ch = tid + p * 256;
                int r = ch >> 3, cq = ch & 7;
                cp_async16(ps + (r * AVW + cq * 4) * 4,
                           PRg + (size_t)r * NREL_ + cq * 8);
            }
            // rel_v transposed: Vs word[d][w] = {relv[2w][d], relv[2w+1][d]}
            uint32_t* vsp = sm3 + st * AVST + AVPT;
            #pragma unroll
            for (int p = 0; p < 8; p++) {
                int idx = tid + p * 256;       // 0..2047
                int d = idx >> 5, w = idx & 31;
                float v0 = __half2float(g_relv_h[(size_t)(2 * w) * DD + d]);
                float v1 = __half2float(g_relv_h[(size_t)(2 * w + 1) * DD + d]);
                vsp[d * AVW + w] = pack_h16(v0, v1);
            }
        }
    };

    float acc[4][4] = {};
    float acc2[4][4] = {};

    issue(0, 0);
    asm volatile("cp.async.commit_group;\n" ::);

    for (int kt = 0; kt < 9; kt++) {
        if (kt + 1 < 9) {
            issue((kt + 1) & 1, kt + 1);
            asm volatile("cp.async.commit_group;\n" ::);
            asm volatile("cp.async.wait_group 1;\n" ::);
        } else {
            asm volatile("cp.async.wait_group 0;\n" ::);
        }
        __syncthreads();

        uint32_t pb = smem_base + ((kt & 1) * AVST) * 4;
        uint32_t vb = pb + AVPT * 4;

        #pragma unroll
        for (int ks = 0; ks < 4; ks++) {
            int kb = ks * 8;
            uint32_t af[4][4];
            #pragma unroll
            for (int mt = 0; mt < 4; mt++) {
                int m = wm * 64 + mt * 16;
                ldmx4(af[mt], pb + ((m + rA) * AVW + kb + kA) * 4);
            }
            uint32_t bt[4];
            ldmx4(bt, vb + ((wn * 16 + rB) * AVW + kb + kB) * 4);
            #pragma unroll
            for (int mt = 0; mt < 4; mt++) {
                mma_f16(acc[mt],  af[mt], &bt[0]);
                mma_f16(acc2[mt], af[mt], &bt[2]);
            }
        }
        __syncthreads();
    }

    #pragma unroll
    for (int mt = 0; mt < 4; mt++) {
        int qa = q0 + wm * 64 + mt * 16 + gid;
        int n0 = wn * 16 + tig * 2;
        size_t w0 = (((size_t)b * SS + qa    ) * HID_ + h * DD + n0) >> 1;
        size_t w1 = (((size_t)b * SS + qa + 8) * HID_ + h * DD + n0) >> 1;
        g_attn16[w0]     = pack_h16(acc[mt][0],  acc[mt][1]);
        g_attn16[w0 + 4] = pack_h16(acc2[mt][0], acc2[mt][1]);
        g_attn16[w1]     = pack_h16(acc[mt][2],  acc[mt][3]);
        g_attn16[w1 + 4] = pack_h16(acc2[mt][2], acc2[mt][3]);
    }
}

// ---------------- launch -----------------------------------------------------
extern "C" void kernel_launch(void* const* d_in, const int* in_sizes, int n_in,
                              void* d_out, int out_size)
{
    const float* q_in = (const float*)d_in[0];
    const float* k_in = (const float*)d_in[1];
    const float* v_in = (const float*)d_in[2];
    const int*   mask = (const int*)  d_in[3];
    const float* Wq   = (const float*)d_in[4];
    const float* bq   = (const float*)d_in[5];
    const float* Wk   = (const float*)d_in[6];
    const float* bk   = (const float*)d_in[7];
    const float* Wv   = (const float*)d_in[8];
    const float* bv   = (const float*)d_in[9];
    const float* Wo   = (const float*)d_in[10];
    const float* bo   = (const float*)d_in[11];
    const float* relk = (const float*)d_in[12];
    const float* relv = (const float*)d_in[13];
    float* out = (float*)d_out;

    void *pQ, *pK, *pV, *pAttn;
    void *pRq, *pRk, *pRv, *pWq, *pWk, *pWv, *pWo, *pRelk, *pRelv;
    cudaGetSymbolAddress(&pQ,    g_Qh);
    cudaGetSymbolAddress(&pK,    g_Kh);
    cudaGetSymbolAddress(&pV,    g_Vh);
    cudaGetSymbolAddress(&pAttn, g_attn16);
    cudaGetSymbolAddress(&pRq,   g_rq);
    cudaGetSymbolAddress(&pRk,   g_rk);
    cudaGetSymbolAddress(&pRv,   g_rv);
    cudaGetSymbolAddress(&pWq,   g_wq);
    cudaGetSymbolAddress(&pWk,   g_wk);
    cudaGetSymbolAddress(&pWv,   g_wv);
    cudaGetSymbolAddress(&pWo,   g_wo);
    cudaGetSymbolAddress(&pRelk, g_relk_h);
    cudaGetSymbolAddress(&pRelv, g_relv_h);

    // 1) fp32 -> fp16 conversion of all GEMM inputs + rel tables
    RoundArgs ra;
    ra.src[0] = (const float4*)q_in; ra.dst[0] = (uint2*)pRq; ra.n4[0] = TT*HID_/4;
    ra.src[1] = (const float4*)k_in; ra.dst[1] = (uint2*)pRk; ra.n4[1] = TT*HID_/4;
    ra.src[2] = (const float4*)v_in; ra.dst[2] = (uint2*)pRv; ra.n4[2] = TT*HID_/4;
    ra.src[3] = (const float4*)Wq;   ra.dst[3] = (uint2*)pWq; ra.n4[3] = HID_*HID_/4;
    ra.src[4] = (const float4*)Wk;   ra.dst[4] = (uint2*)pWk; ra.n4[4] = HID_*HID_/4;
    ra.src[5] = (const float4*)Wv;   ra.dst[5] = (uint2*)pWv; ra.n4[5] = HID_*HID_/4;
    ra.src[6] = (const float4*)Wo;   ra.dst[6] = (uint2*)pWo; ra.n4[6] = HID_*HID_/4;
    ra.src[7] = (const float4*)relk; ra.dst[7] = (uint2*)pRelk; ra.n4[7] = NREL_*DD/4;
    ra.src[8] = (const float4*)relv; ra.dst[8] = (uint2*)pRelv; ra.n4[8] = NREL_*DD/4;
    round_f16_kernel<<<dim3(512, 9), 256>>>(ra);

    const int gemmSmem = 2 * 2 * GTILE * 4;   // 73728 B (proven 2 CTA/SM)
    cudaFuncSetAttribute(h16_gemm_kernel,
                         cudaFuncAttributeMaxDynamicSharedMemorySize, gemmSmem);

    // 2) fused QKV projection (V stored transposed per head)
    GemmArgs qkv;
    qkv.X[0] = (const __half*)pRq; qkv.X[1] = (const __half*)pRk; qkv.X[2] = (const __half*)pRv;
    qkv.W[0] = (const __half*)pWq; qkv.W[1] = (const __half*)pWk; qkv.W[2] = (const __half*)pWv;
    qkv.b[0] = bq;  qkv.b[1] = bk;  qkv.b[2] = bv;
    qkv.O[0] = pQ;  qkv.O[1] = pK;  qkv.O[2] = pV;
    qkv.sc[0] = 1;  qkv.sc[1] = 1;  qkv.sc[2] = 2;
    h16_gemm_kernel<<<dim3(HID_ / GBM, TT / GBM, 3), 256, gemmSmem>>>(qkv);

    // 3) scores = Q @ K^T (+ fused qrel), fp16 out
    const int qkSmem = (256 * QKW + 64 * QKW) * 4;   // 46080 B
    cudaFuncSetAttribute(qk_scores_kernel,
                         cudaFuncAttributeMaxDynamicSharedMemorySize, qkSmem);
    qk_scores_kernel<<<dim3(4, 4, BH), 256, qkSmem>>>();

    // 4) softmax + relation bins
    softmax_kernel<<<BH * SS / 8, 256>>>(mask);

    // 5) AV + relation-V (fp16 MMA, 128-row tiles)
    const int avSmem = 2 * AVST * 4;                 // 55296 B
    cudaFuncSetAttribute(av_kernel,
                         cudaFuncAttributeMaxDynamicSharedMemorySize, avSmem);
    av_kernel<<<dim3(4, BH), 256, avSmem>>>();

    // 6) output projection (fp32 out)
    GemmArgs og;
    og.X[0] = (const __half*)pAttn; og.W[0] = (const __half*)pWo;
    og.b[0] = bo; og.O[0] = out;
    og.X[1] = og.X[2] = nullptr; og.W[1] = og.W[2] = nullptr;
    og.b[1] = og.b[2] = nullptr; og.O[1] = og.O[2] = nullptr;
    og.sc[0] = 0; og.sc[1] = 0; og.sc[2] = 0;
    h16_gemm_kernel<<<dim3(HID_ / GBM, TT / GBM, 1), 256, gemmSmem>>>(og);
}

// round 17
// speedup vs baseline: 1.1807x; 1.0137x over previous
#include <cuda_runtime.h>
#include <cuda_bf16.h>
#include <cuda_fp16.h>
#include <math.h>
#include <stdint.h>

#define BB   4
#define SS   512
#define HID_ 1024
#define HH   16
#define DD   64
#define NREL_ 64
#define TT   (BB*SS)      // 2048 tokens
#define BH   (BB*HH)      // 64

// ---------------- scratch (static device globals; fp16 packed in uint32) ----
__device__ uint32_t g_Qh[BH*SS*DD/2];             // [bh][s][d] fp16
__device__ uint32_t g_Kh[BH*SS*DD/2];             // [bh][s][d] fp16
__device__ __half   g_Vh[BH*SS*DD];               // [bh][d][s] fp16 (TRANSPOSED)
__device__ float    g_qrel[BH*SS*NREL_];          // fp32
__device__ uint32_t g_pr16[BH*SS*NREL_/2];        // 0.25-scaled, fp16
__device__ uint32_t g_s16[(size_t)BH*SS*SS/2];    // raw scores fp16 (32 MB)
__device__ uint32_t g_p16[(size_t)BH*SS*SS/2];    // probs fp16 (32 MB)
__device__ uint32_t g_attn16[TT*HID_/2];          // attention output fp16
__device__ uint8_t  g_mask8[(size_t)BB*SS*SS];    // mask ids as bytes (4 MB)
// fp16 copies of GEMM inputs + rel tables
__device__ uint32_t g_rq[TT*HID_/2];
__device__ uint32_t g_rk[TT*HID_/2];
__device__ uint32_t g_rv[TT*HID_/2];
__device__ uint32_t g_wq[HID_*HID_/2];
__device__ uint32_t g_wk[HID_*HID_/2];
__device__ uint32_t g_wv[HID_*HID_/2];
__device__ uint32_t g_wo[HID_*HID_/2];
__device__ uint32_t g_relk_h[NREL_*DD/2];
__device__ __half   g_relv_h[NREL_*DD];

__device__ __forceinline__ uint32_t pack_h16(float a, float b) {
    __half2 t = __floats2half2_rn(a, b);
    return *(uint32_t*)&t;
}

// ---------------- fp32 -> fp16 conversion + mask byte pass -------------------
struct RoundArgs {
    const float4* src[9];
    uint2*        dst[9];
    int           n4[9];
    const int4*   msrc;
    uint32_t*     mdst;
    int           mn4;
};
__global__ void round_f16_kernel(RoundArgs a)
{
    int seg = blockIdx.y;
    if (seg == 9) {
        // mask int32 -> uint8
        for (int i = blockIdx.x * blockDim.x + threadIdx.x; i < a.mn4;
             i += gridDim.x * blockDim.x) {
            int4 v = a.msrc[i];
            a.mdst[i] = (uint32_t)(v.x & 255) | ((uint32_t)(v.y & 255) << 8)
                      | ((uint32_t)(v.z & 255) << 16) | ((uint32_t)(v.w & 255) << 24);
        }
        return;
    }
    const float4* s = a.src[seg];
    uint2*        d = a.dst[seg];
    int n = a.n4[seg];
    for (int i = blockIdx.x * blockDim.x + threadIdx.x; i < n;
         i += gridDim.x * blockDim.x) {
        float4 v = s[i];
        uint2 o;
        o.x = pack_h16(v.x, v.y);
        o.y = pack_h16(v.z, v.w);
        d[i] = o;
    }
}

// ======================= MMA / cp.async / ldmatrix helpers ===================
__device__ __forceinline__ void mma_f16(float c[4], const uint32_t a[4],
                                        const uint32_t b2[2]) {
    asm volatile(
        "mma.sync.aligned.m16n8k16.row.col.f32.f16.f16.f32 "
        "{%0,%1,%2,%3}, {%4,%5,%6,%7}, {%8,%9}, {%0,%1,%2,%3};"
        : "+f"(c[0]), "+f"(c[1]), "+f"(c[2]), "+f"(c[3])
        : "r"(a[0]), "r"(a[1]), "r"(a[2]), "r"(a[3]),
          "r"(b2[0]), "r"(b2[1]));
}
__device__ __forceinline__ void cp_async16(uint32_t smem, const void* g) {
    asm volatile("cp.async.cg.shared.global [%0], [%1], 16;\n"
                 :: "r"(smem), "l"(g));
}
__device__ __forceinline__ uint32_t smem_u32(const void* p) {
    return (uint32_t)__cvta_generic_to_shared(p);
}
__device__ __forceinline__ void ldmx4(uint32_t* r, uint32_t a) {
    asm volatile("ldmatrix.sync.aligned.m8n8.x4.shared.b16 {%0,%1,%2,%3}, [%4];"
        : "=r"(r[0]), "=r"(r[1]), "=r"(r[2]), "=r"(r[3]) : "r"(a));
}
__device__ __forceinline__ uint32_t h2ex2(uint32_t x) {
    uint32_t r;
    asm("ex2.approx.f16x2 %0, %1;" : "=r"(r) : "r"(x));
    return r;
}

// ======================= fp16 tensor-core GEMM (2-stage, GBK=64) =============
struct GemmArgs {
    const __half* X[3];
    const __half* W[3];
    const float*  b[3];
    void*         O[3];
    int sc[3];
};

#define GBM 128
#define GBK 64                 // halfs per k-tile
#define GLDW 36                // uint32 per smem row (32 data + 4 pad)
#define GTILE (GBM * GLDW)     // words per matrix per stage

__global__ void __launch_bounds__(256, 2)
h16_gemm_kernel(GemmArgs args)
{
    const int K = 1024, N = 1024;
    int mat = blockIdx.z;
    const __half* __restrict__ X    = args.X[mat];
    const __half* __restrict__ W    = args.W[mat];
    const float*  __restrict__ bias = args.b[mat];
    void*                      O    = args.O[mat];
    int sc = args.sc[mat];

    extern __shared__ uint32_t smg[];   // [2 stages][2 mats][128][36]

    int tid  = threadIdx.x;
    int lane = tid & 31;
    int wid  = tid >> 5;
    int wm   = wid & 1;
    int wn   = wid >> 1;
    int gid  = lane >> 2;
    int tig  = lane & 3;

    int rA = lane & 15;
    int kA = (lane >> 4) * 4;
    int rB = (lane & 7) + ((lane >> 1) & 8);
    int kB = (lane >> 1) & 4;

    int row0 = blockIdx.y * GBM;
    int col0 = blockIdx.x * GBM;

    uint32_t smem_base = smem_u32(smg);

    float acc[4][4][4] = {};
    const int KT = K / GBK;   // 16

    auto issue = [&](int st, int k0) {
        uint32_t xs = smem_base + (st * 2 * GTILE) * 4;
        uint32_t ws = xs + GTILE * 4;
        #pragma unroll
        for (int p = 0; p < 4; p++) {
            int ch = tid + p * 256;        // 0..1023
            int r = ch >> 3, cq = ch & 7;  // 8 chunks of 8 halfs per row
            cp_async16(xs + (r * GLDW + cq * 4) * 4,
                       X + (size_t)(row0 + r) * K + k0 + cq * 8);
            cp_async16(ws + (r * GLDW + cq * 4) * 4,
                       W + (size_t)(col0 + r) * K + k0 + cq * 8);
        }
    };

    issue(0, 0);
    asm volatile("cp.async.commit_group;\n" ::);

    for (int kt = 0; kt < KT; kt++) {
        if (kt + 1 < KT) {
            issue((kt + 1) & 1, (kt + 1) * GBK);
            asm volatile("cp.async.commit_group;\n" ::);
            asm volatile("cp.async.wait_group 1;\n" ::);
        } else {
            asm volatile("cp.async.wait_group 0;\n" ::);
        }
        __syncthreads();

        uint32_t xb = smem_base + ((kt & 1) * 2 * GTILE) * 4;
        uint32_t wb = xb + GTILE * 4;

        #pragma unroll
        for (int ks = 0; ks < 4; ks++) {
            int kb = ks * 8;
            uint32_t af[4][4];
            #pragma unroll
            for (int mt = 0; mt < 4; mt++) {
                int m = wm * 64 + mt * 16;
                ldmx4(af[mt], xb + ((m + rA) * GLDW + kb + kA) * 4);
            }
            uint32_t bt[2][4];
            ldmx4(bt[0], wb + ((wn * 32 + rB) * GLDW + kb + kB) * 4);
            ldmx4(bt[1], wb + ((wn * 32 + 16 + rB) * GLDW + kb + kB) * 4);
            #pragma unroll
            for (int mt = 0; mt < 4; mt++) {
                mma_f16(acc[mt][0], af[mt], &bt[0][0]);
                mma_f16(acc[mt][1], af[mt], &bt[0][2]);
                mma_f16(acc[mt][2], af[mt], &bt[1][0]);
                mma_f16(acc[mt][3], af[mt], &bt[1][2]);
            }
        }
        __syncthreads();
    }

    #pragma unroll
    for (int mt = 0; mt < 4; mt++) {
        #pragma unroll
        for (int nt = 0; nt < 4; nt++) {
            int m = row0 + wm * 64 + mt * 16 + gid;
            int n = col0 + wn * 32 + nt * 8 + tig * 2;
            float y00 = acc[mt][nt][0] + bias[n];
            float y01 = acc[mt][nt][1] + bias[n + 1];
            float y10 = acc[mt][nt][2] + bias[n];
            float y11 = acc[mt][nt][3] + bias[n + 1];
            if (sc == 1) {
                uint32_t* Oh = (uint32_t*)O;
                int b = m >> 9, s = m & 511, h = n >> 6, d = n & 63;
                Oh[((((size_t)b * HH + h) * SS + s) * DD + d) >> 1] =
                    pack_h16(y00, y01);
                int s2 = (m + 8) & 511;
                Oh[((((size_t)b * HH + h) * SS + s2) * DD + d) >> 1] =
                    pack_h16(y10, y11);
            } else if (sc == 2) {
                __half* Oh = (__half*)O;
                int b = m >> 9, s = m & 511, h = n >> 6, d = n & 63;
                size_t base = (((size_t)b * HH + h) * DD + d) * SS;
                Oh[base + s]           = __float2half(y00);
                Oh[base + SS + s]      = __float2half(y01);
                Oh[base + s + 8]       = __float2half(y10);
                Oh[base + SS + s + 8]  = __float2half(y11);
            } else {
                float* Of = (float*)O;
                *(float2*)&Of[(size_t)m * N + n]       = make_float2(y00, y01);
                *(float2*)&Of[(size_t)(m + 8) * N + n] = make_float2(y10, y11);
            }
        }
    }
}

// ================= qk_scores (+fused qrel): fp16 MMA, ldmatrix ==============
#define QKW 36    // uint32 per smem row (32 data + 4 pad)

__global__ void __launch_bounds__(256, 2)
qk_scores_kernel()
{
    extern __shared__ uint32_t sm2[];   // Qs[128][36] Ks[128][36] Rs[64][36]
    uint32_t* Qs = sm2;
    uint32_t* Ks = sm2 + 128 * QKW;
    uint32_t* Rs = sm2 + 256 * QKW;

    int tid  = threadIdx.x;
    int lane = tid & 31;
    int wid  = tid >> 5;
    int wm   = wid & 1;
    int wn   = wid >> 1;
    int gid  = lane >> 2;
    int tig  = lane & 3;

    int rA = lane & 15;
    int kA = (lane >> 4) * 4;
    int rB = (lane & 7) + ((lane >> 1) & 8);
    int kB = (lane >> 1) & 4;

    int bh   = blockIdx.z;
    int row0 = blockIdx.y * 128;
    int col0 = blockIdx.x * 128;

    const __half* Qg = (const __half*)g_Qh + (size_t)bh * SS * DD;
    const __half* Kg = (const __half*)g_Kh + (size_t)bh * SS * DD;

    uint32_t qs0 = smem_u32(Qs);
    uint32_t ks0 = smem_u32(Ks);
    uint32_t rs0 = smem_u32(Rs);

    #pragma unroll
    for (int p = 0; p < 4; p++) {
        int ch = tid + p * 256;
        int r = ch >> 3, cq = ch & 7;
        cp_async16(qs0 + (r * QKW + cq * 4) * 4,
                   Qg + (size_t)(row0 + r) * DD + cq * 8);
        cp_async16(ks0 + (r * QKW + cq * 4) * 4,
                   Kg + (size_t)(col0 + r) * DD + cq * 8);
    }
    if (col0 == 0) {
        #pragma unroll
        for (int p = 0; p < 2; p++) {
            int ch = tid + p * 256;
            int r = ch >> 3, cq = ch & 7;
            cp_async16(rs0 + (r * QKW + cq * 4) * 4,
                       (const __half*)g_relk_h + (size_t)r * DD + cq * 8);
        }
    }
    asm volatile("cp.async.commit_group;\n" ::);
    asm volatile("cp.async.wait_group 0;\n" ::);
    __syncthreads();

    // fused qrel (only first n-tile; warps wn<2 cover the 64 rel columns)
    if (col0 == 0 && wn < 2) {
        float acc2[4][4][4] = {};
        #pragma unroll
        for (int ks = 0; ks < 4; ks++) {
            int kb = ks * 8;
            uint32_t af[4][4];
            #pragma unroll
            for (int mt = 0; mt < 4; mt++) {
                int m = wm * 64 + mt * 16;
                ldmx4(af[mt], qs0 + ((m + rA) * QKW + kb + kA) * 4);
            }
            uint32_t bt[2][4];
            ldmx4(bt[0], rs0 + ((wn * 32 + rB) * QKW + kb + kB) * 4);
            ldmx4(bt[1], rs0 + ((wn * 32 + 16 + rB) * QKW + kb + kB) * 4);
            #pragma unroll
            for (int mt = 0; mt < 4; mt++) {
                mma_f16(acc2[mt][0], af[mt], &bt[0][0]);
                mma_f16(acc2[mt][1], af[mt], &bt[0][2]);
                mma_f16(acc2[mt][2], af[mt], &bt[1][0]);
                mma_f16(acc2[mt][3], af[mt], &bt[1][2]);
            }
        }
        #pragma unroll
        for (int mt = 0; mt < 4; mt++) {
            #pragma unroll
            for (int nt = 0; nt < 4; nt++) {
                int m0 = row0 + wm * 64 + mt * 16 + gid;
                int n  = wn * 32 + nt * 8 + tig * 2;
                *(float2*)&g_qrel[((size_t)bh * SS + m0) * NREL_ + n] =
                    make_float2(acc2[mt][nt][0], acc2[mt][nt][1]);
                *(float2*)&g_qrel[((size_t)bh * SS + m0 + 8) * NREL_ + n] =
                    make_float2(acc2[mt][nt][2], acc2[mt][nt][3]);
            }
        }
    }

    float acc[4][4][4] = {};
    #pragma unroll
    for (int ks = 0; ks < 4; ks++) {
        int kb = ks * 8;
        uint32_t af[4][4];
        #pragma unroll
        for (int mt = 0; mt < 4; mt++) {
            int m = wm * 64 + mt * 16;
            ldmx4(af[mt], qs0 + ((m + rA) * QKW + kb + kA) * 4);
        }
        uint32_t bt[2][4];
        ldmx4(bt[0], ks0 + ((wn * 32 + rB) * QKW + kb + kB) * 4);
        ldmx4(bt[1], ks0 + ((wn * 32 + 16 + rB) * QKW + kb + kB) * 4);
        #pragma unroll
        for (int mt = 0; mt < 4; mt++) {
            mma_f16(acc[mt][0], af[mt], &bt[0][0]);
            mma_f16(acc[mt][1], af[mt], &bt[0][2]);
            mma_f16(acc[mt][2], af[mt], &bt[1][0]);
            mma_f16(acc[mt][3], af[mt], &bt[1][2]);
        }
    }

    uint32_t* Og = g_s16 + (size_t)bh * SS * (SS / 2);
    #pragma unroll
    for (int mt = 0; mt < 4; mt++) {
        #pragma unroll
        for (int nt = 0; nt < 4; nt++) {
            int m0 = row0 + wm * 64 + mt * 16 + gid;
            int n  = col0 + wn * 32 + nt * 8 + tig * 2;
            Og[((size_t)m0 * SS + n) >> 1] =
                pack_h16(acc[mt][nt][0], acc[mt][nt][1]);
            Og[((size_t)(m0 + 8) * SS + n) >> 1] =
                pack_h16(acc[mt][nt][2], acc[mt][nt][3]);
        }
    }
}

// ===== softmax: warp/row, single pass, byte mask, ex2.f16x2 ==================
__global__ void __launch_bounds__(256)
softmax_kernel()
{
    __shared__ float qtab[8][64];
    __shared__ float bins[8][64];

    int tid  = threadIdx.x;
    int lane = tid & 31;
    int wid  = tid >> 5;

    int rowg = blockIdx.x * 8 + wid;      // bh*512 + q
    int bh = rowg >> 9;
    int q  = rowg & 511;
    int b  = bh >> 4;

    const float QSC = 0.03125f * 1.44269504f;   // qrel/32 * log2e
    const float CL  = 0.125f   * 1.44269504f;   // score/8 * log2e
    qtab[wid][lane]      = g_qrel[(size_t)rowg * NREL_ + lane]      * QSC;
    qtab[wid][lane + 32] = g_qrel[(size_t)rowg * NREL_ + lane + 32] * QSC;
    bins[wid][lane]      = 0.f;
    bins[wid][lane + 32] = 0.f;
    __syncwarp();

    const uint4* srow  = (const uint4*)(g_s16 + (size_t)rowg * (SS / 2));
    const uint2* m8row = (const uint2*)(g_mask8 + ((size_t)b * SS + q) * SS);
    uint4*       prow  = (uint4*)(g_p16 + (size_t)rowg * (SS / 2));

    float p[16];
    int   ids[16];
    float sum = 0.f;

    #pragma unroll
    for (int hlf = 0; hlf < 2; hlf++) {
        uint4 sv = srow[lane + 32 * hlf];          // 8 fp16 scores
        uint2 mv = m8row[lane + 32 * hlf];         // 8 mask bytes
        float fs[8];
        {
            __half2 t;
            float2 f;
            t = *(__half2*)&sv.x; f = __half22float2(t); fs[0]=f.x; fs[1]=f.y;
            t = *(__half2*)&sv.y; f = __half22float2(t); fs[2]=f.x; fs[3]=f.y;
            t = *(__half2*)&sv.z; f = __half22float2(t); fs[4]=f.x; fs[5]=f.y;
            t = *(__half2*)&sv.w; f = __half22float2(t); fs[6]=f.x; fs[7]=f.y;
        }
        int idv[8];
        idv[0] =  mv.x        & 255;
        idv[1] = (mv.x >>  8) & 255;
        idv[2] = (mv.x >> 16) & 255;
        idv[3] = (mv.x >> 24);
        idv[4] =  mv.y        & 255;
        idv[5] = (mv.y >>  8) & 255;
        idv[6] = (mv.y >> 16) & 255;
        idv[7] = (mv.y >> 24);

        float a[8];
        #pragma unroll
        for (int j = 0; j < 8; j++)
            a[j] = fmaf(fs[j], CL, qtab[wid][idv[j]]);

        uint32_t e[4];
        e[0] = h2ex2(pack_h16(a[0], a[1]));
        e[1] = h2ex2(pack_h16(a[2], a[3]));
        e[2] = h2ex2(pack_h16(a[4], a[5]));
        e[3] = h2ex2(pack_h16(a[6], a[7]));

        #pragma unroll
        for (int j = 0; j < 4; j++) {
            float2 f = __half22float2(*(__half2*)&e[j]);
            int k = hlf * 8 + j * 2;
            float v0 = idv[j * 2]     > 0 ? f.x : 0.f;
            float v1 = idv[j * 2 + 1] > 0 ? f.y : 0.f;
            p[k]     = v0;
            p[k + 1] = v1;
            ids[k]     = idv[j * 2];
            ids[k + 1] = idv[j * 2 + 1];
            sum += v0 + v1;
        }
    }
    #pragma unroll
    for (int o = 16; o; o >>= 1) sum += __shfl_xor_sync(0xffffffffu, sum, o);
    float inv = 1.f / sum;

    #pragma unroll
    for (int hlf = 0; hlf < 2; hlf++) {
        int k = hlf * 8;
        uint4 o;
        o.x = pack_h16(p[k+0] * inv, p[k+1] * inv);
        o.y = pack_h16(p[k+2] * inv, p[k+3] * inv);
        o.z = pack_h16(p[k+4] * inv, p[k+5] * inv);
        o.w = pack_h16(p[k+6] * inv, p[k+7] * inv);
        prow[lane + 32 * hlf] = o;
    }
    #pragma unroll
    for (int k = 0; k < 16; k++)
        atomicAdd(&bins[wid][ids[k]], p[k]);
    __syncwarp();

    float sc = 0.25f * inv;
    g_pr16[(size_t)rowg * (NREL_ / 2) + lane] =
        pack_h16(sc * bins[wid][2 * lane], sc * bins[wid][2 * lane + 1]);
}

// ===== av: out = probs @ V + pr' @ rel_v (fp16 MMA, 128-row, ldmatrix) ======
#define AVW 36
#define AVPT (128 * AVW)     // P tile words per stage
#define AVVT (64 * AVW)      // V tile words per stage
#define AVST (AVPT + AVVT)

__global__ void __launch_bounds__(256)
av_kernel()
{
    extern __shared__ uint32_t sm3[];   // [2][Ps 128x36 | Vs 64x36]

    int tid  = threadIdx.x;
    int lane = tid & 31;
    int wid  = tid >> 5;
    int wm   = wid & 1;
    int wn   = wid >> 1;
    int gid  = lane >> 2;
    int tig  = lane & 3;

    int rA = lane & 15;
    int kA = (lane >> 4) * 4;
    int rB = (lane & 7) + ((lane >> 1) & 8);
    int kB = (lane >> 1) & 4;

    int bh = blockIdx.y;
    int q0 = blockIdx.x * 128;
    int b  = bh >> 4, h = bh & 15;

    uint32_t smem_base = smem_u32(sm3);

    const __half* Pg  = (const __half*)g_p16 + (size_t)bh * SS * SS;
    const __half* PRg = (const __half*)g_pr16 + ((size_t)bh * SS + q0) * NREL_;
    const __half* Vg  = g_Vh + (size_t)bh * SS * DD;   // [d][s]

    auto issue = [&](int st, int kt) {
        uint32_t ps = smem_base + (st * AVST) * 4;
        uint32_t vs = ps + AVPT * 4;
        if (kt < 8) {
            #pragma unroll
            for (int p = 0; p < 4; p++) {
                int ch = tid + p * 256;        // 0..1023
                int r = ch >> 3, cq = ch & 7;
                cp_async16(ps + (r * AVW + cq * 4) * 4,
                           Pg + (size_t)(q0 + r) * SS + kt * 64 + cq * 8);
            }
            #pragma unroll
            for (int p = 0; p < 2; p++) {
                int ch = tid + p * 256;        // 0..511
                int r = ch >> 3, cq = ch & 7;
                cp_async16(vs + (r * AVW + cq * 4) * 4,
                           Vg + (size_t)r * SS + kt * 64 + cq * 8);
            }
        } else {
            #pragma unroll
            for (int p = 0; p < 4; p++) {
                int ch = tid + p * 256;
                int r = ch >> 3, cq = ch & 7;
                cp_async16(ps + (r * AVW + cq * 4) * 4,
                           PRg + (size_t)r * NREL_ + cq * 8);
            }
            // rel_v transposed: Vs word[d][w] = {relv[2w][d], relv[2w+1][d]}
            uint32_t* vsp = sm3 + st * AVST + AVPT;
            #pragma unroll
            for (int p = 0; p < 8; p++) {
                int idx = tid + p * 256;       // 0..2047
                int d = idx >> 5, w = idx & 31;
                float v0 = __half2float(g_relv_h[(size_t)(2 * w) * DD + d]);
                float v1 = __half2float(g_relv_h[(size_t)(2 * w + 1) * DD + d]);
                vsp[d * AVW + w] = pack_h16(v0, v1);
            }
        }
    };

    float acc[4][4] = {};
    float acc2[4][4] = {};

    issue(0, 0);
    asm volatile("cp.async.commit_group;\n" ::);

    for (int kt = 0; kt < 9; kt++) {
        if (kt + 1 < 9) {
            issue((kt + 1) & 1, kt + 1);
            asm volatile("cp.async.commit_group;\n" ::);
            asm volatile("cp.async.wait_group 1;\n" ::);
        } else {
            asm volatile("cp.async.wait_group 0;\n" ::);
        }
        __syncthreads();

        uint32_t pb = smem_base + ((kt & 1) * AVST) * 4;
        uint32_t vb = pb + AVPT * 4;

        #pragma unroll
        for (int ks = 0; ks < 4; ks++) {
            int kb = ks * 8;
            uint32_t af[4][4];
            #pragma unroll
            for (int mt = 0; mt < 4; mt++) {
                int m = wm * 64 + mt * 16;
                ldmx4(af[mt], pb + ((m + rA) * AVW + kb + kA) * 4);
            }
            uint32_t bt[4];
            ldmx4(bt, vb + ((wn * 16 + rB) * AVW + kb + kB) * 4);
            #pragma unroll
            for (int mt = 0; mt < 4; mt++) {
                mma_f16(acc[mt],  af[mt], &bt[0]);
                mma_f16(acc2[mt], af[mt], &bt[2]);
            }
        }
        __syncthreads();
    }

    #pragma unroll
    for (int mt = 0; mt < 4; mt++) {
        int qa = q0 + wm * 64 + mt * 16 + gid;
        int n0 = wn * 16 + tig * 2;
        size_t w0 = (((size_t)b * SS + qa    ) * HID_ + h * DD + n0) >> 1;
        size_t w1 = (((size_t)b * SS + qa + 8) * HID_ + h * DD + n0) >> 1;
        g_attn16[w0]     = pack_h16(acc[mt][0],  acc[mt][1]);
        g_attn16[w0 + 4] = pack_h16(acc2[mt][0], acc2[mt][1]);
        g_attn16[w1]     = pack_h16(acc[mt][2],  acc[mt][3]);
        g_attn16[w1 + 4] = pack_h16(acc2[mt][2], acc2[mt][3]);
    }
}

// ---------------- launch -----------------------------------------------------
extern "C" void kernel_launch(void* const* d_in, const int* in_sizes, int n_in,
                              void* d_out, int out_size)
{
    const float* q_in = (const float*)d_in[0];
    const float* k_in = (const float*)d_in[1];
    const float* v_in = (const float*)d_in[2];
    const int*   mask = (const int*)  d_in[3];
    const float* Wq   = (const float*)d_in[4];
    const float* bq   = (const float*)d_in[5];
    const float* Wk   = (const float*)d_in[6];
    const float* bk   = (const float*)d_in[7];
    const float* Wv   = (const float*)d_in[8];
    const float* bv   = (const float*)d_in[9];
    const float* Wo   = (const float*)d_in[10];
    const float* bo   = (const float*)d_in[11];
    const float* relk = (const float*)d_in[12];
    const float* relv = (const float*)d_in[13];
    float* out = (float*)d_out;

    void *pQ, *pK, *pV, *pAttn, *pM8;
    void *pRq, *pRk, *pRv, *pWq, *pWk, *pWv, *pWo, *pRelk, *pRelv;
    cudaGetSymbolAddress(&pQ,    g_Qh);
    cudaGetSymbolAddress(&pK,    g_Kh);
    cudaGetSymbolAddress(&pV,    g_Vh);
    cudaGetSymbolAddress(&pAttn, g_attn16);
    cudaGetSymbolAddress(&pM8,   g_mask8);
    cudaGetSymbolAddress(&pRq,   g_rq);
    cudaGetSymbolAddress(&pRk,   g_rk);
    cudaGetSymbolAddress(&pRv,   g_rv);
    cudaGetSymbolAddress(&pWq,   g_wq);
    cudaGetSymbolAddress(&pWk,   g_wk);
    cudaGetSymbolAddress(&pWv,   g_wv);
    cudaGetSymbolAddress(&pWo,   g_wo);
    cudaGetSymbolAddress(&pRelk, g_relk_h);
    cudaGetSymbolAddress(&pRelv, g_relv_h);

    // 1) fp32 -> fp16 conversion + mask byte pass
    RoundArgs ra;
    ra.src[0] = (const float4*)q_in; ra.dst[0] = (uint2*)pRq; ra.n4[0] = TT*HID_/4;
    ra.src[1] = (const float4*)k_in; ra.dst[1] = (uint2*)pRk; ra.n4[1] = TT*HID_/4;
    ra.src[2] = (const float4*)v_in; ra.dst[2] = (uint2*)pRv; ra.n4[2] = TT*HID_/4;
    ra.src[3] = (const float4*)Wq;   ra.dst[3] = (uint2*)pWq; ra.n4[3] = HID_*HID_/4;
    ra.src[4] = (const float4*)Wk;   ra.dst[4] = (uint2*)pWk; ra.n4[4] = HID_*HID_/4;
    ra.src[5] = (const float4*)Wv;   ra.dst[5] = (uint2*)pWv; ra.n4[5] = HID_*HID_/4;
    ra.src[6] = (const float4*)Wo;   ra.dst[6] = (uint2*)pWo; ra.n4[6] = HID_*HID_/4;
    ra.src[7] = (const float4*)relk; ra.dst[7] = (uint2*)pRelk; ra.n4[7] = NREL_*DD/4;
    ra.src[8] = (const float4*)relv; ra.dst[8] = (uint2*)pRelv; ra.n4[8] = NREL_*DD/4;
    ra.msrc = (const int4*)mask; ra.mdst = (uint32_t*)pM8;
    ra.mn4  = BB * SS * SS / 4;
    round_f16_kernel<<<dim3(512, 10), 256>>>(ra);

    const int gemmSmem = 2 * 2 * GTILE * 4;   // 73728 B (proven 2 CTA/SM)
    cudaFuncSetAttribute(h16_gemm_kernel,
                         cudaFuncAttributeMaxDynamicSharedMemorySize, gemmSmem);

    // 2) fused QKV projection (V stored transposed per head)
    GemmArgs qkv;
    qkv.X[0] = (const __half*)pRq; qkv.X[1] = (const __half*)pRk; qkv.X[2] = (const __half*)pRv;
    qkv.W[0] = (const __half*)pWq; qkv.W[1] = (const __half*)pWk; qkv.W[2] = (const __half*)pWv;
    qkv.b[0] = bq;  qkv.b[1] = bk;  qkv.b[2] = bv;
    qkv.O[0] = pQ;  qkv.O[1] = pK;  qkv.O[2] = pV;
    qkv.sc[0] = 1;  qkv.sc[1] = 1;  qkv.sc[2] = 2;
    h16_gemm_kernel<<<dim3(HID_ / GBM, TT / GBM, 3), 256, gemmSmem>>>(qkv);

    // 3) scores = Q @ K^T (+ fused qrel), fp16 out
    const int qkSmem = (256 * QKW + 64 * QKW) * 4;   // 46080 B
    cudaFuncSetAttribute(qk_scores_kernel,
                         cudaFuncAttributeMaxDynamicSharedMemorySize, qkSmem);
    qk_scores_kernel<<<dim3(4, 4, BH), 256, qkSmem>>>();

    // 4) softmax + relation bins (byte mask, f16x2 exp)
    softmax_kernel<<<BH * SS / 8, 256>>>();

    // 5) AV + relation-V (fp16 MMA, 128-row tiles)
    const int avSmem = 2 * AVST * 4;                 // 55296 B
    cudaFuncSetAttribute(av_kernel,
                         cudaFuncAttributeMaxDynamicSharedMemorySize, avSmem);
    av_kernel<<<dim3(4, BH), 256, avSmem>>>();

    // 6) output projection (fp32 out)
    GemmArgs og;
    og.X[0] = (const __half*)pAttn; og.W[0] = (const __half*)pWo;
    og.b[0] = bo; og.O[0] = out;
    og.X[1] = og.X[2] = nullptr; og.W[1] = og.W[2] = nullptr;
    og.b[1] = og.b[2] = nullptr; og.O[1] = og.O[2] = nullptr;
    og.sc[0] = 0; og.sc[1] = 0; og.sc[2] = 0;
    h16_gemm_kernel<<<dim3(HID_ / GBM, TT / GBM, 1), 256, gemmSmem>>>(og);
}